// round 12
// baseline (speedup 1.0000x reference)
#include <cuda_runtime.h>
#include <cuda_bf16.h>
#include <math.h>
#include <stdint.h>

#define B_  2
#define L_  1024
#define DM  1024
#define DI  2048
#define NH  32
#define HD  64
#define DS  128
#define NA  32
#define DP  4480   // 2*DI + 2*DS + 3*NH + NA
#define BT  (B_*L_)

#define K1X (3*DM)      // gemm1 folded K' = 3072
#define K2X (3*DI)      // gemm2 folded K' = 6144

// ---------------- device scratch ----------------
__device__ float g_proj[(size_t)BT * DP];
__device__ float g_Bn  [BT * DS];
__device__ float g_Cn  [BT * DS];
__device__ float g_dt  [BT * NH];
__device__ float g_gd  [BT * NH];
__device__ float g_lam [BT * NH];
__device__ float g_y   [(size_t)BT * DI];
__device__ float g_cos [BT * NH * NA];
__device__ float g_sin [BT * NH * NA];
__device__ float g_csum[B_ * 32 * NH * NA];
__device__ float g_cpre[B_ * 32 * NH * NA];

__device__ __nv_bfloat16 g_u2 [(size_t)BT * K1X];
__device__ __nv_bfloat16 g_Wi2[(size_t)DP * K1X];
__device__ __nv_bfloat16 g_y2 [(size_t)BT * K2X];
__device__ __nv_bfloat16 g_Wo2[(size_t)DM * K2X];

typedef unsigned long long ull;

__device__ __forceinline__ float softplusf(float x) {
    return (x > 20.f) ? x : log1pf(expf(x));
}
__device__ __forceinline__ uint32_t smem_u32(const void* p) {
    uint32_t a;
    asm("{ .reg .u64 t; cvta.to.shared.u64 t, %1; cvt.u32.u64 %0, t; }" : "=r"(a) : "l"(p));
    return a;
}

// ---- packed f32x2 helpers ----
__device__ __forceinline__ ull pk2(float v) {
    ull r; asm("mov.b64 %0, {%1, %1};" : "=l"(r) : "f"(v)); return r;
}
__device__ __forceinline__ ull fma2(ull a, ull b, ull c) {
    ull d; asm("fma.rn.f32x2 %0, %1, %2, %3;" : "=l"(d) : "l"(a), "l"(b), "l"(c)); return d;
}
__device__ __forceinline__ ull mul2(ull a, ull b) {
    ull d; asm("mul.rn.f32x2 %0, %1, %2;" : "=l"(d) : "l"(a), "l"(b)); return d;
}
__device__ __forceinline__ float sum2(ull a) {
    float x, y;
    asm("mov.b64 {%0, %1}, %2;" : "=f"(x), "=f"(y) : "l"(a));
    return x + y;
}

#define CP_ASYNC16(dst, src) \
    asm volatile("cp.async.cg.shared.global [%0], [%1], 16;" :: "r"(dst), "l"(src))
#define CP_ASYNC4(dst, src) \
    asm volatile("cp.async.ca.shared.global [%0], [%1], 4;" :: "r"(dst), "l"(src))
#define CP_COMMIT() asm volatile("cp.async.commit_group;")
#define CP_WAIT2()  asm volatile("cp.async.wait_group 2;")
#define CP_WAIT1()  asm volatile("cp.async.wait_group 1;")
#define CP_WAIT0()  asm volatile("cp.async.wait_group 0;")

__device__ __forceinline__ void ldsm_x4(uint32_t* r, uint32_t addr) {
    asm volatile("ldmatrix.sync.aligned.m8n8.x4.shared.b16 {%0,%1,%2,%3}, [%4];"
        : "=r"(r[0]), "=r"(r[1]), "=r"(r[2]), "=r"(r[3]) : "r"(addr));
}
__device__ __forceinline__ void mma16816(float* d, const uint32_t* a, const uint32_t* b) {
    asm volatile(
        "mma.sync.aligned.m16n8k16.row.col.f32.bf16.bf16.f32 "
        "{%0,%1,%2,%3},{%4,%5,%6,%7},{%8,%9},{%0,%1,%2,%3};"
        : "+f"(d[0]), "+f"(d[1]), "+f"(d[2]), "+f"(d[3])
        : "r"(a[0]), "r"(a[1]), "r"(a[2]), "r"(a[3]), "r"(b[0]), "r"(b[1]));
}

// ---------------- split kernels ----------------
__global__ __launch_bounds__(256) void split_A(
    const float* __restrict__ src, __nv_bfloat16* __restrict__ dst, int Kq, int n4)
{
    int i = blockIdx.x * 256 + threadIdx.x;
    if (i >= n4) return;
    int row = i / Kq, k4 = (i - row * Kq) * 4;
    float4 v = *(const float4*)(src + (size_t)row * (Kq * 4) + k4);
    __nv_bfloat162 h01 = __floats2bfloat162_rn(v.x, v.y);
    __nv_bfloat162 h23 = __floats2bfloat162_rn(v.z, v.w);
    __nv_bfloat162 l01 = __floats2bfloat162_rn(v.x - __low2float(h01), v.y - __high2float(h01));
    __nv_bfloat162 l23 = __floats2bfloat162_rn(v.z - __low2float(h23), v.w - __high2float(h23));
    const int K = Kq * 4;
    __nv_bfloat162* d0 = (__nv_bfloat162*)(dst + (size_t)row * 3 * K + k4);
    __nv_bfloat162* d1 = (__nv_bfloat162*)(dst + (size_t)row * 3 * K + K + k4);
    __nv_bfloat162* d2 = (__nv_bfloat162*)(dst + (size_t)row * 3 * K + 2 * K + k4);
    d0[0] = h01; d0[1] = h23;
    d1[0] = l01; d1[1] = l23;
    d2[0] = h01; d2[1] = h23;
}
__global__ __launch_bounds__(256) void split_B(
    const float* __restrict__ src, __nv_bfloat16* __restrict__ dst, int Kq, int n4)
{
    int i = blockIdx.x * 256 + threadIdx.x;
    if (i >= n4) return;
    int row = i / Kq, k4 = (i - row * Kq) * 4;
    float4 v = *(const float4*)(src + (size_t)row * (Kq * 4) + k4);
    __nv_bfloat162 h01 = __floats2bfloat162_rn(v.x, v.y);
    __nv_bfloat162 h23 = __floats2bfloat162_rn(v.z, v.w);
    __nv_bfloat162 l01 = __floats2bfloat162_rn(v.x - __low2float(h01), v.y - __high2float(h01));
    __nv_bfloat162 l23 = __floats2bfloat162_rn(v.z - __low2float(h23), v.w - __high2float(h23));
    const int K = Kq * 4;
    __nv_bfloat162* d0 = (__nv_bfloat162*)(dst + (size_t)row * 3 * K + k4);
    __nv_bfloat162* d1 = (__nv_bfloat162*)(dst + (size_t)row * 3 * K + K + k4);
    __nv_bfloat162* d2 = (__nv_bfloat162*)(dst + (size_t)row * 3 * K + 2 * K + k4);
    d0[0] = h01; d0[1] = h23;
    d1[0] = h01; d1[1] = h23;
    d2[0] = l01; d2[1] = l23;
}

// ---------------- bf16 mma.sync GEMM: 3-stage cp.async pipeline ----------------
#define GS_STAGE 32768
#define GS_TOTAL (3 * GS_STAGE + 1024)

__global__ __launch_bounds__(256) void gemm_bf16(
    const __nv_bfloat16* __restrict__ A, const __nv_bfloat16* __restrict__ Bm,
    float* __restrict__ C, int M, int N, int K)
{
    extern __shared__ char dynsmem[];
    const int tid = threadIdx.x;
    const int wid = tid >> 5, lane = tid & 31;
    const int bm = blockIdx.y * 128, bn = blockIdx.x * 128;
    const int m_warp = (wid >> 1) * 32, n_warp = (wid & 1) * 64;

    uint32_t raw = smem_u32(dynsmem);
    const uint32_t sbase = (raw + 1023u) & ~1023u;

    uint32_t psw[4];
    const __nv_bfloat16 *Ap[4], *Bp[4];
#pragma unroll
    for (int i = 0; i < 4; i++) {
        const int chunk = tid + i * 256;
        const int row = chunk >> 3, c = chunk & 7;
        psw[i] = row * 128 + ((c ^ (row & 7)) << 4);
        Ap[i] = A  + (size_t)(bm + row) * K + c * 8;
        Bp[i] = Bm + (size_t)(bn + row) * K + c * 8;
    }

    const int khA = lane >> 4;
    const int rA0 = m_warp + (lane & 15), rA1 = rA0 + 16;
    const uint32_t offA0 = rA0 * 128, offA1 = rA1 * 128;
    const int x7A0 = rA0 & 7, x7A1 = rA1 & 7;
    const int khB = (lane >> 3) & 1;
    const int rb_off = (lane & 7) + ((lane >> 4) << 3);
    uint32_t offB[4]; int x7B[4];
#pragma unroll
    for (int np = 0; np < 4; np++) {
        const int r = n_warp + np * 16 + rb_off;
        offB[np] = r * 128; x7B[np] = r & 7;
    }

    float acc[2][8][4];
#pragma unroll
    for (int mt = 0; mt < 2; mt++)
#pragma unroll
        for (int nt = 0; nt < 8; nt++)
#pragma unroll
            for (int e = 0; e < 4; e++) acc[mt][nt][e] = 0.f;

    const int nk = K >> 6;

#pragma unroll
    for (int st = 0; st < 2; st++) {
        const uint32_t s = sbase + st * GS_STAGE;
        const int ko = st << 6;
#pragma unroll
        for (int i = 0; i < 4; i++) {
            CP_ASYNC16(s + psw[i], Ap[i] + ko);
            CP_ASYNC16(s + 16384 + psw[i], Bp[i] + ko);
        }
        CP_COMMIT();
    }

    int buf = 0, pb = 2;
    for (int kc = 0; kc < nk; kc++) {
        if (kc + 2 < nk) {
            const uint32_t s = sbase + pb * GS_STAGE;
            const int ko = (kc + 2) << 6;
#pragma unroll
            for (int i = 0; i < 4; i++) {
                CP_ASYNC16(s + psw[i], Ap[i] + ko);
                CP_ASYNC16(s + 16384 + psw[i], Bp[i] + ko);
            }
            CP_COMMIT();
            CP_WAIT2();
            pb = (pb == 2) ? 0 : pb + 1;
        } else if (kc + 1 < nk) {
            CP_WAIT1();
        } else {
            CP_WAIT0();
        }
        __syncthreads();

        const uint32_t sA = sbase + buf * GS_STAGE;
        const uint32_t sB = sA + 16384;
#pragma unroll
        for (int ks = 0; ks < 4; ks++) {
            uint32_t a0[4], a1[4];
            const int cA = 2 * ks + khA;
            ldsm_x4(a0, sA + offA0 + ((cA ^ x7A0) << 4));
            ldsm_x4(a1, sA + offA1 + ((cA ^ x7A1) << 4));
            uint32_t b[8][2];
            const int cB = 2 * ks + khB;
#pragma unroll
            for (int np = 0; np < 4; np++) {
                uint32_t r[4];
                ldsm_x4(r, sB + offB[np] + ((cB ^ x7B[np]) << 4));
                b[2 * np][0] = r[0]; b[2 * np][1] = r[1];
                b[2 * np + 1][0] = r[2]; b[2 * np + 1][1] = r[3];
            }
#pragma unroll
            for (int nt = 0; nt < 8; nt++) {
                mma16816(acc[0][nt], a0, b[nt]);
                mma16816(acc[1][nt], a1, b[nt]);
            }
        }
        __syncthreads();
        buf = (buf == 2) ? 0 : buf + 1;
    }

    const int tr = lane >> 2, tc = (lane & 3) * 2;
#pragma unroll
    for (int mt = 0; mt < 2; mt++) {
        const int row0 = bm + m_warp + mt * 16 + tr;
#pragma unroll
        for (int nt = 0; nt < 8; nt++) {
            const int col = bn + n_warp + nt * 8 + tc;
            *(float2*)(C + (size_t)row0 * N + col)       = make_float2(acc[mt][nt][0], acc[mt][nt][1]);
            *(float2*)(C + (size_t)(row0 + 8) * N + col) = make_float2(acc[mt][nt][2], acc[mt][nt][3]);
        }
    }
}

// ---------------- prep ----------------
__global__ __launch_bounds__(128) void prep_kernel(
    const float* __restrict__ dt_bias,
    const float* __restrict__ Bnw, const float* __restrict__ Cnw)
{
    const int bt = blockIdx.x;
    const int n  = threadIdx.x;
    const size_t base = (size_t)bt * DP;

    float Bv = g_proj[base + 2 * DI + n];
    float Cv = g_proj[base + 2 * DI + DS + n];
    float sb = Bv * Bv, sc = Cv * Cv;
#pragma unroll
    for (int o = 16; o > 0; o >>= 1) {
        sb += __shfl_xor_sync(0xffffffffu, sb, o);
        sc += __shfl_xor_sync(0xffffffffu, sc, o);
    }
    __shared__ float red[2][4];
    const int w = n >> 5, ln = n & 31;
    if (ln == 0) { red[0][w] = sb; red[1][w] = sc; }
    __syncthreads();
    float tb = red[0][0] + red[0][1] + red[0][2] + red[0][3];
    float tc = red[1][0] + red[1][1] + red[1][2] + red[1][3];

    g_Bn[bt * DS + n] = Bv * rsqrtf(tb * (1.f / DS) + 1e-5f) * Bnw[n];
    g_Cn[bt * DS + n] = Cv * rsqrtf(tc * (1.f / DS) + 1e-5f) * Cnw[n];

    if (n < NH) {
        float dd = g_proj[base + 2 * DI + 2 * DS + n];
        float dA = g_proj[base + 2 * DI + 2 * DS + NH + n];
        float tr = g_proj[base + 2 * DI + 2 * DS + 2 * NH + n];
        float dt = softplusf(dd + dt_bias[n]);
        float a  = -softplusf(dA);
        a = fminf(a, -1e-4f);
        g_dt [bt * NH + n] = dt;
        g_gd [bt * NH + n] = expf(a * dt);
        g_lam[bt * NH + n] = 1.f / (1.f + expf(-tr));
    }
}

// ---------------- theta: parallel 3-pass ----------------
__global__ __launch_bounds__(1024) void thetaA_kernel()
{
    const int c = blockIdx.x, b = blockIdx.y;
    __shared__ float sdt[1024], sang[1024];
    const int i = threadIdx.x;
    const int bt0 = b * L_ + c * 32;
    sdt[i] = g_dt[bt0 * NH + i];
    const int s = i >> 5, j = i & 31;
    sang[i] = g_proj[(size_t)(bt0 + s) * DP + (DP - NA) + j];
    __syncthreads();
    const int h = i >> 5;
    float acc = 0.f;
#pragma unroll
    for (int ss = 0; ss < 32; ss++)
        acc = fmaf(sdt[ss * 32 + h], sang[ss * 32 + j], acc);
    g_csum[(b * 32 + c) * 1024 + i] = acc;
}

__global__ __launch_bounds__(1024) void thetaB_kernel()
{
    const int b = blockIdx.x, i = threadIdx.x;
    float run = 0.f;
    for (int c = 0; c < 32; c++) {
        float v = g_csum[(b * 32 + c) * 1024 + i];
        g_cpre[(b * 32 + c) * 1024 + i] = run;
        run += v;
    }
}

__global__ __launch_bounds__(1024) void thetaC_kernel()
{
    const int c = blockIdx.x, b = blockIdx.y;
    __shared__ float sdt[1024], sang[1024];
    const int i = threadIdx.x;
    const int bt0 = b * L_ + c * 32;
    sdt[i] = g_dt[bt0 * NH + i];
    const int s0 = i >> 5, j = i & 31;
    sang[i] = g_proj[(size_t)(bt0 + s0) * DP + (DP - NA) + j];
    __syncthreads();
    const int h = i >> 5;
    float run = g_cpre[(b * 32 + c) * 1024 + i];
#pragma unroll
    for (int s = 0; s < 32; s++) {
        run = fmaf(sdt[s * 32 + h], sang[s * 32 + j], run);
        float sn, cs;
        __sincosf(run, &sn, &cs);
        const int o = (bt0 + s) * 1024 + i;
        g_cos[o] = cs;
        g_sin[o] = sn;
    }
}

// ---------------- tiled sequential SSM scan: 256 threads, 8 p-groups ----------------
// pg = tid>>5 (0..7): p rows [pg*4, pg*4+4). ng = tid&31: n chunk [ng*4, +4) = 2 f32x2.
// LDS/step: B 16B + C 16B per thread (8 KB total) + broadcast x.
#define ST 32
#define NTILE (L_ / ST)

struct __align__(16) ScanSmem {
    float sB[2][ST][128];     // 32 KB
    float sC[2][ST][128];     // 32 KB
    float sCs[2][ST][32];     // 8 KB
    float sSn[2][ST][32];     // 8 KB
    float sX[2][ST][32];      // 8 KB
    float sScal[2][3][ST];    // 768 B
    float sYp[ST][32][8];     // 32 KB
};
#define SCAN_SMEM_BYTES ((int)sizeof(ScanSmem))

__global__ __launch_bounds__(256) void scan_kernel(
    const float* __restrict__ Bbias, const float* __restrict__ Cbias)
{
    extern __shared__ char dynsmem[];
    ScanSmem* s = (ScanSmem*)dynsmem;

    const int phalf = blockIdx.x;
    const int h = blockIdx.y;
    const int b = blockIdx.z;
    const int tid = threadIdx.x;
    const int pg = tid >> 5;         // 0..7
    const int ng = tid & 31;         // 0..31
    const int n0 = ng * 4;
    const int pstart = phalf * 32;

    // rope-stage role: tid<128 -> B, else C; 64 threads per row, 2 rows per pass
    const int nn = tid & 63;
    const int tq = (tid >> 6) & 1;
    const float* biasPtr = (tid < 128) ? Bbias : Cbias;
    float ba1, ba2;
    if (nn < 32) { ba1 = biasPtr[h * DS + nn];      ba2 = biasPtr[h * DS + nn + 32]; }
    else         { ba1 = biasPtr[h * DS + nn + 32]; ba2 = biasPtr[h * DS + nn + 64]; }

#define PREFETCH(k, pbuf) do {                                                   \
        const int bt0_ = b * L_ + (k) * ST;                                      \
        _Pragma("unroll")                                                        \
        for (int r = 0; r < 4; r++) {                                            \
            const int q = tid + r * 256, tp = q >> 5, seg = q & 31;              \
            CP_ASYNC16(smem_u32(&s->sB[pbuf][tp][seg * 4]),                      \
                       &g_Bn[(bt0_ + tp) * DS + seg * 4]);                       \
            CP_ASYNC16(smem_u32(&s->sC[pbuf][tp][seg * 4]),                      \
                       &g_Cn[(bt0_ + tp) * DS + seg * 4]);                       \
        }                                                                        \
        {                                                                        \
            const int tp = tid >> 3, seg = tid & 7;                              \
            CP_ASYNC16(smem_u32(&s->sCs[pbuf][tp][seg * 4]),                     \
                       &g_cos[((bt0_ + tp) * NH + h) * NA + seg * 4]);           \
            CP_ASYNC16(smem_u32(&s->sSn[pbuf][tp][seg * 4]),                     \
                       &g_sin[((bt0_ + tp) * NH + h) * NA + seg * 4]);           \
            CP_ASYNC16(smem_u32(&s->sX[pbuf][tp][seg * 4]),                      \
                       &g_proj[(size_t)(bt0_ + tp) * DP + DI + h * HD + pstart + seg * 4]); \
        }                                                                        \
        if (tid < 96) {                                                          \
            const int which = tid >> 5, tp = tid & 31;                           \
            const float* srcs = (which == 0) ? g_dt : (which == 1) ? g_gd : g_lam; \
            CP_ASYNC4(smem_u32(&s->sScal[pbuf][which][tp]),                      \
                      &srcs[(bt0_ + tp) * NH + h]);                              \
        }                                                                        \
        CP_COMMIT();                                                             \
    } while (0)

    ull hs[4][2], Bp[2];
#pragma unroll
    for (int p = 0; p < 4; p++) { hs[p][0] = 0ull; hs[p][1] = 0ull; }
    Bp[0] = 0ull; Bp[1] = 0ull;
    float xp[4] = {0.f, 0.f, 0.f, 0.f};

    PREFETCH(0, 0);

    for (int k = 0; k < NTILE; k++) {
        const int buf = k & 1;
        if (k + 1 < NTILE) {
            PREFETCH(k + 1, buf ^ 1);
            CP_WAIT1();
        } else {
            CP_WAIT0();
        }
        __syncthreads();

        // ---- bias + RoPE stage (128 threads per matrix, 2 rows per pass) ----
        {
            float* mat = (tid < 128) ? &s->sB[buf][0][0] : &s->sC[buf][0][0];
#pragma unroll
            for (int tp = tq; tp < ST; tp += 2) {
                float* rb = mat + tp * 128;
                if (nn < 32) {
                    const float cv = s->sCs[buf][tp][nn], sv = s->sSn[buf][tp][nn];
                    const float v1 = rb[nn] + ba1, v2 = rb[nn + 32] + ba2;
                    rb[nn]      = v1 * cv - v2 * sv;
                    rb[nn + 32] = v1 * sv + v2 * cv;
                } else {
                    rb[nn + 32] += ba1;
                    rb[nn + 64] += ba2;
                }
            }
        }
        __syncthreads();

        // ---- 32 timesteps: state update, partial-y to smem ----
#pragma unroll 8
        for (int tp = 0; tp < ST; tp++) {
            const float dt  = s->sScal[buf][0][tp];
            const float g   = s->sScal[buf][1][tp];
            const float lam = s->sScal[buf][2][tp];
            const float4 xc = *(const float4*)&s->sX[buf][tp][pg * 4];
            const float k1 = dt * lam;
            const float k2 = dt * (1.f - lam) * g;
            const ull g2 = pk2(g);

            const ulonglong2 bvv = *(const ulonglong2*)&s->sB[buf][tp][n0];
            const ulonglong2 cvv = *(const ulonglong2*)&s->sC[buf][tp][n0];
            const ull bv[2] = { bvv.x, bvv.y };
            const ull cv[2] = { cvv.x, cvv.y };
            const float xcv[4] = { xc.x, xc.y, xc.z, xc.w };

            float yout[4];
#pragma unroll
            for (int p = 0; p < 4; p++) {
                const ull c1 = pk2(k1 * xcv[p]);
                const ull c2 = pk2(k2 * xp[p]);
                ull y = 0ull;
#pragma unroll
                for (int j = 0; j < 2; j++) {
                    ull t0 = mul2(c2, Bp[j]);
                    t0 = fma2(c1, bv[j], t0);
                    hs[p][j] = fma2(g2, hs[p][j], t0);
                    y = fma2(hs[p][j], cv[j], y);
                }
                xp[p] = xcv[p];
                yout[p] = sum2(y);
            }
            Bp[0] = bv[0]; Bp[1] = bv[1];

#pragma unroll
            for (int p = 0; p < 4; p++) {
                yout[p] += __shfl_xor_sync(0xffffffffu, yout[p], 8);
                yout[p] += __shfl_xor_sync(0xffffffffu, yout[p], 16);
            }
            if (ng < 8) {
#pragma unroll
                for (int p = 0; p < 4; p++)
                    s->sYp[tp][pg * 4 + p][ng] = yout[p];
            }
        }
        __syncthreads();

        // ---- batched per-tile reduce: 1024 (t,p) pairs, 4 per thread ----
#pragma unroll
        for (int r = 0; r < 4; r++) {
            const int idx = tid + r * 256;
            const int t  = idx >> 5;        // 0..31
            const int p0 = idx & 31;        // 0..31
            float4 a0 = *(const float4*)&s->sYp[t][p0][0];
            float4 a1 = *(const float4*)&s->sYp[t][p0][4];
            float v0 = (a0.x + a0.y) + (a0.z + a0.w) + (a1.x + a1.y) + (a1.z + a1.w);
            g_y[(size_t)(b * L_ + k * ST + t) * DI + h * HD + pstart + p0] = v0;
        }
        __syncthreads();
    }
#undef PREFETCH
}

// ---------------- epilogue ----------------
__global__ __launch_bounds__(256) void epi_kernel(const float* __restrict__ Dp)
{
    const int idx = blockIdx.x * 256 + threadIdx.x;
    const int bt = idx >> 11;
    const int c  = idx & 2047;
    const int h  = c >> 6;
    float y = g_y[idx];
    float x = g_proj[(size_t)bt * DP + DI + c];
    float z = g_proj[(size_t)bt * DP + c];
    float sil = z / (1.f + expf(-z));
    float v = (y + Dp[h] * x) * sil;
    __nv_bfloat16 hh = __float2bfloat16(v);
    __nv_bfloat16 ll = __float2bfloat16(v - __bfloat162float(hh));
    const size_t rb = (size_t)bt * K2X;
    g_y2[rb + c]          = hh;
    g_y2[rb + DI + c]     = ll;
    g_y2[rb + 2 * DI + c] = hh;
}

// ---------------- launch ----------------
extern "C" void kernel_launch(void* const* d_in, const int* in_sizes, int n_in,
                              void* d_out, int out_size)
{
    (void)in_sizes; (void)n_in; (void)out_size;
    const float* u        = (const float*)d_in[0];
    const float* W_in     = (const float*)d_in[1];
    const float* W_out    = (const float*)d_in[2];
    const float* dt_bias  = (const float*)d_in[3];
    const float* B_bias   = (const float*)d_in[4];
    const float* C_bias   = (const float*)d_in[5];
    const float* B_norm_w = (const float*)d_in[6];
    const float* C_norm_w = (const float*)d_in[7];
    const float* D_param  = (const float*)d_in[8];
    float* out = (float*)d_out;

    void *p_proj, *p_u2, *p_wi2, *p_y2, *p_wo2;
    cudaGetSymbolAddress(&p_proj, g_proj);
    cudaGetSymbolAddress(&p_u2,  g_u2);
    cudaGetSymbolAddress(&p_wi2, g_Wi2);
    cudaGetSymbolAddress(&p_y2,  g_y2);
    cudaGetSymbolAddress(&p_wo2, g_Wo2);

    cudaFuncSetAttribute(gemm_bf16, cudaFuncAttributeMaxDynamicSharedMemorySize, GS_TOTAL);
    cudaFuncSetAttribute(scan_kernel, cudaFuncAttributeMaxDynamicSharedMemorySize, SCAN_SMEM_BYTES);

    // 0) folded bf16 splits
    split_A<<<(BT * DM / 4 + 255) / 256, 256>>>(u,     (__nv_bfloat16*)p_u2,  DM / 4, BT * DM / 4);
    split_B<<<(DP * DM / 4 + 255) / 256, 256>>>(W_in,  (__nv_bfloat16*)p_wi2, DM / 4, DP * DM / 4);
    split_B<<<(DM * DI / 4 + 255) / 256, 256>>>(W_out, (__nv_bfloat16*)p_wo2, DI / 4, DM * DI / 4);

    // 1) proj = u @ W_in^T
    gemm_bf16<<<dim3(DP / 128, BT / 128), 256, GS_TOTAL>>>(
        (const __nv_bfloat16*)p_u2, (const __nv_bfloat16*)p_wi2,
        (float*)p_proj, BT, DP, K1X);

    // 2) rmsnorm + head scalars
    prep_kernel<<<BT, 128>>>(dt_bias, B_norm_w, C_norm_w);

    // 3) theta: parallel chunked cumsum + sincos
    thetaA_kernel<<<dim3(32, B_), 1024>>>();
    thetaB_kernel<<<B_, 1024>>>();
    thetaC_kernel<<<dim3(32, B_), 1024>>>();

    // 4) tiled sequential scan (256 threads, 8 p-groups, ST=32)
    scan_kernel<<<dim3(2, NH, B_), 256, SCAN_SMEM_BYTES>>>(B_bias, C_bias);

    // 5) gated epilogue
    epi_kernel<<<(BT * DI) / 256, 256>>>(D_param);

    // 6) out = yact @ W_out^T
    gemm_bf16<<<dim3(DM / 128, BT / 128), 256, GS_TOTAL>>>(
        (const __nv_bfloat16*)p_y2, (const __nv_bfloat16*)p_wo2,
        out, BT, DM, K2X);
}

// round 13
// speedup vs baseline: 1.1859x; 1.1859x over previous
#include <cuda_runtime.h>
#include <cuda_bf16.h>
#include <math.h>
#include <stdint.h>

#define B_  2
#define L_  1024
#define DM  1024
#define DI  2048
#define NH  32
#define HD  64
#define DS  128
#define NA  32
#define DP  4480   // 2*DI + 2*DS + 3*NH + NA
#define BT  (B_*L_)

#define K1X (3*DM)      // gemm1 folded K' = 3072
#define K2X (3*DI)      // gemm2 folded K' = 6144

typedef unsigned long long ull;

// ---------------- device scratch ----------------
__device__ float g_proj[(size_t)BT * DP];
__device__ float g_Bn  [BT * DS];
__device__ float g_Cn  [BT * DS];
__device__ float g_dt  [BT * NH];
__device__ float g_gd  [BT * NH];
__device__ float g_lam [BT * NH];
__device__ float g_y   [(size_t)BT * DI];
__device__ float g_cos [BT * NH * NA];
__device__ float g_sin [BT * NH * NA];
__device__ float g_csum[B_ * 32 * NH * NA];
__device__ float g_cpre[B_ * 32 * NH * NA];
__device__ float g_Ct  [(size_t)B_ * NH * 512 * 128];   // chunk-1 roped C (16.8 MB)
__device__ ull   g_hend[(size_t)B_ * NH * 2 * 256 * 8]; // chunk-0 end state (2 MB)

__device__ __nv_bfloat16 g_u2 [(size_t)BT * K1X];
__device__ __nv_bfloat16 g_Wi2[(size_t)DP * K1X];
__device__ __nv_bfloat16 g_y2 [(size_t)BT * K2X];
__device__ __nv_bfloat16 g_Wo2[(size_t)DM * K2X];

__device__ __forceinline__ float softplusf(float x) {
    return (x > 20.f) ? x : log1pf(expf(x));
}
__device__ __forceinline__ uint32_t smem_u32(const void* p) {
    uint32_t a;
    asm("{ .reg .u64 t; cvta.to.shared.u64 t, %1; cvt.u32.u64 %0, t; }" : "=r"(a) : "l"(p));
    return a;
}

// ---- packed f32x2 helpers ----
__device__ __forceinline__ ull pk2(float v) {
    ull r; asm("mov.b64 %0, {%1, %1};" : "=l"(r) : "f"(v)); return r;
}
__device__ __forceinline__ ull pk2two(float lo, float hi) {
    ull r; asm("mov.b64 %0, {%1, %2};" : "=l"(r) : "f"(lo), "f"(hi)); return r;
}
__device__ __forceinline__ ull fma2(ull a, ull b, ull c) {
    ull d; asm("fma.rn.f32x2 %0, %1, %2, %3;" : "=l"(d) : "l"(a), "l"(b), "l"(c)); return d;
}
__device__ __forceinline__ ull mul2(ull a, ull b) {
    ull d; asm("mul.rn.f32x2 %0, %1, %2;" : "=l"(d) : "l"(a), "l"(b)); return d;
}
__device__ __forceinline__ float sum2(ull a) {
    float x, y;
    asm("mov.b64 {%0, %1}, %2;" : "=f"(x), "=f"(y) : "l"(a));
    return x + y;
}

#define CP_ASYNC16(dst, src) \
    asm volatile("cp.async.cg.shared.global [%0], [%1], 16;" :: "r"(dst), "l"(src))
#define CP_ASYNC4(dst, src) \
    asm volatile("cp.async.ca.shared.global [%0], [%1], 4;" :: "r"(dst), "l"(src))
#define CP_COMMIT() asm volatile("cp.async.commit_group;")
#define CP_WAIT1()  asm volatile("cp.async.wait_group 1;")
#define CP_WAIT0()  asm volatile("cp.async.wait_group 0;")

__device__ __forceinline__ void ldsm_x4(uint32_t* r, uint32_t addr) {
    asm volatile("ldmatrix.sync.aligned.m8n8.x4.shared.b16 {%0,%1,%2,%3}, [%4];"
        : "=r"(r[0]), "=r"(r[1]), "=r"(r[2]), "=r"(r[3]) : "r"(addr));
}
__device__ __forceinline__ void mma16816(float* d, const uint32_t* a, const uint32_t* b) {
    asm volatile(
        "mma.sync.aligned.m16n8k16.row.col.f32.bf16.bf16.f32 "
        "{%0,%1,%2,%3},{%4,%5,%6,%7},{%8,%9},{%0,%1,%2,%3};"
        : "+f"(d[0]), "+f"(d[1]), "+f"(d[2]), "+f"(d[3])
        : "r"(a[0]), "r"(a[1]), "r"(a[2]), "r"(a[3]), "r"(b[0]), "r"(b[1]));
}

// ---------------- split kernels ----------------
__global__ __launch_bounds__(256) void split_A(
    const float* __restrict__ src, __nv_bfloat16* __restrict__ dst, int Kq, int n4)
{
    int i = blockIdx.x * 256 + threadIdx.x;
    if (i >= n4) return;
    int row = i / Kq, k4 = (i - row * Kq) * 4;
    float4 v = *(const float4*)(src + (size_t)row * (Kq * 4) + k4);
    __nv_bfloat162 h01 = __floats2bfloat162_rn(v.x, v.y);
    __nv_bfloat162 h23 = __floats2bfloat162_rn(v.z, v.w);
    __nv_bfloat162 l01 = __floats2bfloat162_rn(v.x - __low2float(h01), v.y - __high2float(h01));
    __nv_bfloat162 l23 = __floats2bfloat162_rn(v.z - __low2float(h23), v.w - __high2float(h23));
    const int K = Kq * 4;
    __nv_bfloat162* d0 = (__nv_bfloat162*)(dst + (size_t)row * 3 * K + k4);
    __nv_bfloat162* d1 = (__nv_bfloat162*)(dst + (size_t)row * 3 * K + K + k4);
    __nv_bfloat162* d2 = (__nv_bfloat162*)(dst + (size_t)row * 3 * K + 2 * K + k4);
    d0[0] = h01; d0[1] = h23;
    d1[0] = l01; d1[1] = l23;
    d2[0] = h01; d2[1] = h23;
}
__global__ __launch_bounds__(256) void split_B(
    const float* __restrict__ src, __nv_bfloat16* __restrict__ dst, int Kq, int n4)
{
    int i = blockIdx.x * 256 + threadIdx.x;
    if (i >= n4) return;
    int row = i / Kq, k4 = (i - row * Kq) * 4;
    float4 v = *(const float4*)(src + (size_t)row * (Kq * 4) + k4);
    __nv_bfloat162 h01 = __floats2bfloat162_rn(v.x, v.y);
    __nv_bfloat162 h23 = __floats2bfloat162_rn(v.z, v.w);
    __nv_bfloat162 l01 = __floats2bfloat162_rn(v.x - __low2float(h01), v.y - __high2float(h01));
    __nv_bfloat162 l23 = __floats2bfloat162_rn(v.z - __low2float(h23), v.w - __high2float(h23));
    const int K = Kq * 4;
    __nv_bfloat162* d0 = (__nv_bfloat162*)(dst + (size_t)row * 3 * K + k4);
    __nv_bfloat162* d1 = (__nv_bfloat162*)(dst + (size_t)row * 3 * K + K + k4);
    __nv_bfloat162* d2 = (__nv_bfloat162*)(dst + (size_t)row * 3 * K + 2 * K + k4);
    d0[0] = h01; d0[1] = h23;
    d1[0] = h01; d1[1] = h23;
    d2[0] = l01; d2[1] = l23;
}

// ---------------- bf16 mma.sync GEMM (R8 2-stage, unchanged) ----------------
#define GS_STAGE 32768
#define GS_TOTAL (2 * GS_STAGE + 1024)

__global__ __launch_bounds__(256) void gemm_bf16(
    const __nv_bfloat16* __restrict__ A, const __nv_bfloat16* __restrict__ Bm,
    float* __restrict__ C, int M, int N, int K)
{
    extern __shared__ char dynsmem[];
    const int tid = threadIdx.x;
    const int wid = tid >> 5, lane = tid & 31;
    const int bm = blockIdx.y * 128, bn = blockIdx.x * 128;
    const int m_warp = (wid >> 1) * 32, n_warp = (wid & 1) * 64;

    uint32_t raw = smem_u32(dynsmem);
    const uint32_t sbase = (raw + 1023u) & ~1023u;

    uint32_t psw[4];
    const __nv_bfloat16 *Ap[4], *Bp[4];
#pragma unroll
    for (int i = 0; i < 4; i++) {
        const int chunk = tid + i * 256;
        const int row = chunk >> 3, c = chunk & 7;
        psw[i] = row * 128 + ((c ^ (row & 7)) << 4);
        Ap[i] = A  + (size_t)(bm + row) * K + c * 8;
        Bp[i] = Bm + (size_t)(bn + row) * K + c * 8;
    }

    const int khA = lane >> 4;
    const int rA0 = m_warp + (lane & 15), rA1 = rA0 + 16;
    const uint32_t offA0 = rA0 * 128, offA1 = rA1 * 128;
    const int x7A0 = rA0 & 7, x7A1 = rA1 & 7;
    const int khB = (lane >> 3) & 1;
    const int rb_off = (lane & 7) + ((lane >> 4) << 3);
    uint32_t offB[4]; int x7B[4];
#pragma unroll
    for (int np = 0; np < 4; np++) {
        const int r = n_warp + np * 16 + rb_off;
        offB[np] = r * 128; x7B[np] = r & 7;
    }

    float acc[2][8][4];
#pragma unroll
    for (int mt = 0; mt < 2; mt++)
#pragma unroll
        for (int nt = 0; nt < 8; nt++)
#pragma unroll
            for (int e = 0; e < 4; e++) acc[mt][nt][e] = 0.f;

    const int nk = K >> 6;
    {
        const uint32_t s = sbase;
#pragma unroll
        for (int i = 0; i < 4; i++) {
            CP_ASYNC16(s + psw[i], Ap[i]);
            CP_ASYNC16(s + 16384 + psw[i], Bp[i]);
        }
        CP_COMMIT();
    }

    for (int kc = 0; kc < nk; kc++) {
        const int buf = kc & 1;
        if (kc + 1 < nk) {
            const uint32_t s = sbase + (buf ^ 1) * GS_STAGE;
            const int ko = (kc + 1) << 6;
#pragma unroll
            for (int i = 0; i < 4; i++) {
                CP_ASYNC16(s + psw[i], Ap[i] + ko);
                CP_ASYNC16(s + 16384 + psw[i], Bp[i] + ko);
            }
            CP_COMMIT();
            CP_WAIT1();
        } else {
            CP_WAIT0();
        }
        __syncthreads();

        const uint32_t sA = sbase + buf * GS_STAGE;
        const uint32_t sB = sA + 16384;
#pragma unroll
        for (int ks = 0; ks < 4; ks++) {
            uint32_t a0[4], a1[4];
            const int cA = 2 * ks + khA;
            ldsm_x4(a0, sA + offA0 + ((cA ^ x7A0) << 4));
            ldsm_x4(a1, sA + offA1 + ((cA ^ x7A1) << 4));
            uint32_t b[8][2];
            const int cB = 2 * ks + khB;
#pragma unroll
            for (int np = 0; np < 4; np++) {
                uint32_t r[4];
                ldsm_x4(r, sB + offB[np] + ((cB ^ x7B[np]) << 4));
                b[2 * np][0] = r[0]; b[2 * np][1] = r[1];
                b[2 * np + 1][0] = r[2]; b[2 * np + 1][1] = r[3];
            }
#pragma unroll
            for (int nt = 0; nt < 8; nt++) {
                mma16816(acc[0][nt], a0, b[nt]);
                mma16816(acc[1][nt], a1, b[nt]);
            }
        }
        __syncthreads();
    }

    const int tr = lane >> 2, tc = (lane & 3) * 2;
#pragma unroll
    for (int mt = 0; mt < 2; mt++) {
        const int row0 = bm + m_warp + mt * 16 + tr;
#pragma unroll
        for (int nt = 0; nt < 8; nt++) {
            const int col = bn + n_warp + nt * 8 + tc;
            *(float2*)(C + (size_t)row0 * N + col)       = make_float2(acc[mt][nt][0], acc[mt][nt][1]);
            *(float2*)(C + (size_t)(row0 + 8) * N + col) = make_float2(acc[mt][nt][2], acc[mt][nt][3]);
        }
    }
}

// ---------------- prep ----------------
__global__ __launch_bounds__(128) void prep_kernel(
    const float* __restrict__ dt_bias,
    const float* __restrict__ Bnw, const float* __restrict__ Cnw)
{
    const int bt = blockIdx.x;
    const int n  = threadIdx.x;
    const size_t base = (size_t)bt * DP;

    float Bv = g_proj[base + 2 * DI + n];
    float Cv = g_proj[base + 2 * DI + DS + n];
    float sb = Bv * Bv, sc = Cv * Cv;
#pragma unroll
    for (int o = 16; o > 0; o >>= 1) {
        sb += __shfl_xor_sync(0xffffffffu, sb, o);
        sc += __shfl_xor_sync(0xffffffffu, sc, o);
    }
    __shared__ float red[2][4];
    const int w = n >> 5, ln = n & 31;
    if (ln == 0) { red[0][w] = sb; red[1][w] = sc; }
    __syncthreads();
    float tb = red[0][0] + red[0][1] + red[0][2] + red[0][3];
    float tc = red[1][0] + red[1][1] + red[1][2] + red[1][3];

    g_Bn[bt * DS + n] = Bv * rsqrtf(tb * (1.f / DS) + 1e-5f) * Bnw[n];
    g_Cn[bt * DS + n] = Cv * rsqrtf(tc * (1.f / DS) + 1e-5f) * Cnw[n];

    if (n < NH) {
        float dd = g_proj[base + 2 * DI + 2 * DS + n];
        float dA = g_proj[base + 2 * DI + 2 * DS + NH + n];
        float tr = g_proj[base + 2 * DI + 2 * DS + 2 * NH + n];
        float dt = softplusf(dd + dt_bias[n]);
        float a  = -softplusf(dA);
        a = fminf(a, -1e-4f);
        g_dt [bt * NH + n] = dt;
        g_gd [bt * NH + n] = expf(a * dt);
        g_lam[bt * NH + n] = 1.f / (1.f + expf(-tr));
    }
}

// ---------------- theta: parallel 3-pass ----------------
__global__ __launch_bounds__(1024) void thetaA_kernel()
{
    const int c = blockIdx.x, b = blockIdx.y;
    __shared__ float sdt[1024], sang[1024];
    const int i = threadIdx.x;
    const int bt0 = b * L_ + c * 32;
    sdt[i] = g_dt[bt0 * NH + i];
    const int s = i >> 5, j = i & 31;
    sang[i] = g_proj[(size_t)(bt0 + s) * DP + (DP - NA) + j];
    __syncthreads();
    const int h = i >> 5;
    float acc = 0.f;
#pragma unroll
    for (int ss = 0; ss < 32; ss++)
        acc = fmaf(sdt[ss * 32 + h], sang[ss * 32 + j], acc);
    g_csum[(b * 32 + c) * 1024 + i] = acc;
}

__global__ __launch_bounds__(1024) void thetaB_kernel()
{
    const int b = blockIdx.x, i = threadIdx.x;
    float run = 0.f;
    for (int c = 0; c < 32; c++) {
        float v = g_csum[(b * 32 + c) * 1024 + i];
        g_cpre[(b * 32 + c) * 1024 + i] = run;
        run += v;
    }
}

__global__ __launch_bounds__(1024) void thetaC_kernel()
{
    const int c = blockIdx.x, b = blockIdx.y;
    __shared__ float sdt[1024], sang[1024];
    const int i = threadIdx.x;
    const int bt0 = b * L_ + c * 32;
    sdt[i] = g_dt[bt0 * NH + i];
    const int s0 = i >> 5, j = i & 31;
    sang[i] = g_proj[(size_t)(bt0 + s0) * DP + (DP - NA) + j];
    __syncthreads();
    const int h = i >> 5;
    float run = g_cpre[(b * 32 + c) * 1024 + i];
#pragma unroll
    for (int s = 0; s < 32; s++) {
        run = fmaf(sdt[s * 32 + h], sang[s * 32 + j], run);
        float sn, cs;
        __sincosf(run, &sn, &cs);
        const int o = (bt0 + s) * 1024 + i;
        g_cos[o] = cs;
        g_sin[o] = sn;
    }
}

// ---------------- chunked tiled SSM scan (R8 core, 2 L-chunks in parallel) ----------------
// blockIdx.x: bit0 = phalf, bit1 = chunk. Chunk c covers t in [c*512, c*512+512).
// Chunk 1 starts with h_in = 0 (corrected later) but EXACT bx_prev from t=511.
#define ST 16
#define NTILE (L_ / ST)
#define HTILE (NTILE / 2)

struct __align__(16) ScanSmem {
    float sB[2][ST][128];
    float sC[2][ST][128];
    float sCs[2][ST][32];
    float sSn[2][ST][32];
    float sX[2][ST][32];
    float sScal[2][3][ST];
    float sYp[ST][32][8];
};
#define SCAN_SMEM_BYTES ((int)sizeof(ScanSmem))

__global__ __launch_bounds__(256) void scan_kernel(
    const float* __restrict__ Bbias, const float* __restrict__ Cbias)
{
    extern __shared__ char dynsmem[];
    ScanSmem* s = (ScanSmem*)dynsmem;

    const int phalf = blockIdx.x & 1;
    const int chunk = blockIdx.x >> 1;
    const int h = blockIdx.y;
    const int b = blockIdx.z;
    const int tid = threadIdx.x;
    const int pp = tid >> 4;
    const int ng = tid & 15;
    const int n0 = ng * 8;
    const int pstart = phalf * 32;
    const int K0 = chunk * HTILE;

    const int nn = tid & 63;
    const int tq = (tid >> 6) & 1;
    const float* biasPtr = (tid < 128) ? Bbias : Cbias;
    float ba1, ba2;
    if (nn < 32) { ba1 = biasPtr[h * DS + nn];      ba2 = biasPtr[h * DS + nn + 32]; }
    else         { ba1 = biasPtr[h * DS + nn + 32]; ba2 = biasPtr[h * DS + nn + 64]; }

#define PREFETCH(k, pbuf) do {                                                   \
        const int bt0_ = b * L_ + (k) * ST;                                      \
        _Pragma("unroll")                                                        \
        for (int r = 0; r < 2; r++) {                                            \
            const int q = tid + r * 256, tp = q >> 5, seg = q & 31;              \
            CP_ASYNC16(smem_u32(&s->sB[pbuf][tp][seg * 4]),                      \
                       &g_Bn[(bt0_ + tp) * DS + seg * 4]);                       \
            CP_ASYNC16(smem_u32(&s->sC[pbuf][tp][seg * 4]),                      \
                       &g_Cn[(bt0_ + tp) * DS + seg * 4]);                       \
        }                                                                        \
        if (tid < 128) {                                                         \
            const int tp = tid >> 3, seg = tid & 7;                              \
            CP_ASYNC16(smem_u32(&s->sCs[pbuf][tp][seg * 4]),                     \
                       &g_cos[((bt0_ + tp) * NH + h) * NA + seg * 4]);           \
            CP_ASYNC16(smem_u32(&s->sSn[pbuf][tp][seg * 4]),                     \
                       &g_sin[((bt0_ + tp) * NH + h) * NA + seg * 4]);           \
            CP_ASYNC16(smem_u32(&s->sX[pbuf][tp][seg * 4]),                      \
                       &g_proj[(size_t)(bt0_ + tp) * DP + DI + h * HD + pstart + seg * 4]); \
        }                                                                        \
        if (tid < 48) {                                                          \
            const int which = tid >> 4, tp = tid & 15;                           \
            const float* srcs = (which == 0) ? g_dt : (which == 1) ? g_gd : g_lam; \
            CP_ASYNC4(smem_u32(&s->sScal[pbuf][which][tp]),                      \
                      &srcs[(bt0_ + tp) * NH + h]);                              \
        }                                                                        \
        CP_COMMIT();                                                             \
    } while (0)

    ull h0[4], h1[4], Bp[4];
#pragma unroll
    for (int i = 0; i < 4; i++) { h0[i] = 0ull; h1[i] = 0ull; Bp[i] = 0ull; }
    float xp0 = 0.f, xp1 = 0.f;

    // Chunk-1: exact bx_prev init from t = 511 (h_in stays 0; corrected later).
    if (chunk == 1) {
        const int bt511 = b * L_ + (L_ / 2 - 1);
        xp0 = g_proj[(size_t)bt511 * DP + DI + h * HD + pstart + pp];
        xp1 = g_proj[(size_t)bt511 * DP + DI + h * HD + pstart + pp + 16];
        float bq[8];
#pragma unroll
        for (int i = 0; i < 8; i++) {
            const int n = n0 + i;
            float v;
            if (n < 32) {
                const float cn = g_cos[(bt511 * NH + h) * NA + n];
                const float sn = g_sin[(bt511 * NH + h) * NA + n];
                const float v1 = g_Bn[bt511 * DS + n]      + Bbias[h * DS + n];
                const float v2 = g_Bn[bt511 * DS + n + 32] + Bbias[h * DS + n + 32];
                v = v1 * cn - v2 * sn;
            } else if (n < 64) {
                const int j = n - 32;
                const float cn = g_cos[(bt511 * NH + h) * NA + j];
                const float sn = g_sin[(bt511 * NH + h) * NA + j];
                const float v1 = g_Bn[bt511 * DS + j] + Bbias[h * DS + j];
                const float v2 = g_Bn[bt511 * DS + n] + Bbias[h * DS + n];
                v = v1 * sn + v2 * cn;
            } else {
                v = g_Bn[bt511 * DS + n] + Bbias[h * DS + n];
            }
            bq[i] = v;
        }
        Bp[0] = pk2two(bq[0], bq[1]); Bp[1] = pk2two(bq[2], bq[3]);
        Bp[2] = pk2two(bq[4], bq[5]); Bp[3] = pk2two(bq[6], bq[7]);
    }

    PREFETCH(K0, 0);

    for (int kk = 0; kk < HTILE; kk++) {
        const int k = K0 + kk;
        const int buf = kk & 1;
        if (kk + 1 < HTILE) {
            PREFETCH(k + 1, buf ^ 1);
            CP_WAIT1();
        } else {
            CP_WAIT0();
        }
        __syncthreads();

        // ---- bias + RoPE stage ----
        {
            float* mat = (tid < 128) ? &s->sB[buf][0][0] : &s->sC[buf][0][0];
#pragma unroll
            for (int tp = tq; tp < ST; tp += 2) {
                float* rb = mat + tp * 128;
                if (nn < 32) {
                    const float cv = s->sCs[buf][tp][nn], sv = s->sSn[buf][tp][nn];
                    const float v1 = rb[nn] + ba1, v2 = rb[nn + 32] + ba2;
                    rb[nn]      = v1 * cv - v2 * sv;
                    rb[nn + 32] = v1 * sv + v2 * cv;
                } else {
                    rb[nn + 32] += ba1;
                    rb[nn + 64] += ba2;
                }
            }
        }
        __syncthreads();

        // chunk-1 / phalf-0 CTA also persists roped C for the correction pass
        if (chunk == 1 && phalf == 0) {
            const int tl = tid >> 4, nc = (tid & 15) * 8;
            const size_t cb = ((size_t)(b * NH + h) * 512 + (k - HTILE) * ST + tl) * 128 + nc;
            *(float4*)&g_Ct[cb]     = *(const float4*)&s->sC[buf][tl][nc];
            *(float4*)&g_Ct[cb + 4] = *(const float4*)&s->sC[buf][tl][nc + 4];
        }

        // ---- 16 timesteps: state update, partial-y to smem ----
#pragma unroll
        for (int tp = 0; tp < ST; tp++) {
            const float dt  = s->sScal[buf][0][tp];
            const float g   = s->sScal[buf][1][tp];
            const float lam = s->sScal[buf][2][tp];
            const float xc0 = s->sX[buf][tp][pp];
            const float xc1 = s->sX[buf][tp][pp + 16];
            const float k1 = dt * lam;
            const float k2 = dt * (1.f - lam) * g;
            const ull g2  = pk2(g);
            const ull c1a = pk2(k1 * xc0);
            const ull c2a = pk2(k2 * xp0);
            const ull c1b = pk2(k1 * xc1);
            const ull c2b = pk2(k2 * xp1);

            const ulonglong2 b01 = *(const ulonglong2*)&s->sB[buf][tp][n0];
            const ulonglong2 b23 = *(const ulonglong2*)&s->sB[buf][tp][n0 + 4];
            const ulonglong2 c01 = *(const ulonglong2*)&s->sC[buf][tp][n0];
            const ulonglong2 c23 = *(const ulonglong2*)&s->sC[buf][tp][n0 + 4];
            const ull bv[4] = { b01.x, b01.y, b23.x, b23.y };
            const ull cv[4] = { c01.x, c01.y, c23.x, c23.y };

            ull y0 = 0ull, y1 = 0ull;
#pragma unroll
            for (int j = 0; j < 4; j++) {
                ull t0 = mul2(c2a, Bp[j]);
                t0 = fma2(c1a, bv[j], t0);
                h0[j] = fma2(g2, h0[j], t0);
                y0 = fma2(h0[j], cv[j], y0);
                ull t1 = mul2(c2b, Bp[j]);
                t1 = fma2(c1b, bv[j], t1);
                h1[j] = fma2(g2, h1[j], t1);
                y1 = fma2(h1[j], cv[j], y1);
                Bp[j] = bv[j];
            }
            xp0 = xc0; xp1 = xc1;

            float y0f = sum2(y0), y1f = sum2(y1);
            y0f += __shfl_xor_sync(0xffffffffu, y0f, 8);
            y1f += __shfl_xor_sync(0xffffffffu, y1f, 8);
            if ((ng & 8) == 0) {
                s->sYp[tp][pp][ng]      = y0f;
                s->sYp[tp][pp + 16][ng] = y1f;
            }
        }
        __syncthreads();

        // ---- batched per-tile reduce ----
        {
            const int t  = tid >> 4;
            const int p0 = (tid & 15) * 2;
            float4 a0 = *(const float4*)&s->sYp[t][p0][0];
            float4 a1 = *(const float4*)&s->sYp[t][p0][4];
            float4 b0 = *(const float4*)&s->sYp[t][p0 + 1][0];
            float4 b1 = *(const float4*)&s->sYp[t][p0 + 1][4];
            float v0 = (a0.x + a0.y) + (a0.z + a0.w) + (a1.x + a1.y) + (a1.z + a1.w);
            float v1 = (b0.x + b0.y) + (b0.z + b0.w) + (b1.x + b1.y) + (b1.z + b1.w);
            *(float2*)&g_y[(size_t)(b * L_ + k * ST + t) * DI + h * HD + pstart + p0] =
                make_float2(v0, v1);
        }
        __syncthreads();
    }
#undef PREFETCH

    // chunk-0 CTA publishes its end state (h at t = 511) for the correction pass
    if (chunk == 0) {
        ull* hd = g_hend + ((size_t)((b * NH + h) * 2 + phalf) * 256 + tid) * 8;
        hd[0] = h0[0]; hd[1] = h0[1]; hd[2] = h0[2]; hd[3] = h0[3];
        hd[4] = h1[0]; hd[5] = h1[1]; hd[6] = h1[2]; hd[7] = h1[3];
    }
}

// ---------------- correction: y_t += P_t * (C~_t . h_in) for t in [512, 1024) ----------------
__global__ __launch_bounds__(256) void correct_kernel()
{
    const int phalf = blockIdx.x;
    const int h = blockIdx.y;
    const int b = blockIdx.z;
    const int tid = threadIdx.x;
    const int pp = tid >> 4;
    const int ng = tid & 15;
    const int n0 = ng * 8;
    const int pstart = phalf * 32;

    __shared__ float sGd[512];
    __shared__ float sYp[16][32][8];

    const ull* hd = g_hend + ((size_t)((b * NH + h) * 2 + phalf) * 256 + tid) * 8;
    ull h0[4], h1[4];
#pragma unroll
    for (int j = 0; j < 4; j++) { h0[j] = hd[j]; h1[j] = hd[4 + j]; }

    for (int i = tid; i < 512; i += 256)
        sGd[i] = g_gd[(b * L_ + 512 + i) * NH + h];
    __syncthreads();

    float P = 1.f;
    for (int kt = 0; kt < 32; kt++) {
#pragma unroll
        for (int tl = 0; tl < 16; tl++) {
            const int ti = kt * 16 + tl;
            P *= sGd[ti];
            const size_t cb = ((size_t)(b * NH + h) * 512 + ti) * 128 + n0;
            const ulonglong2 cc0 = *(const ulonglong2*)&g_Ct[cb];
            const ulonglong2 cc1 = *(const ulonglong2*)&g_Ct[cb + 4];
            const ull cv[4] = { cc0.x, cc0.y, cc1.x, cc1.y };
            ull y0 = 0ull, y1 = 0ull;
#pragma unroll
            for (int j = 0; j < 4; j++) {
                y0 = fma2(h0[j], cv[j], y0);
                y1 = fma2(h1[j], cv[j], y1);
            }
            float y0f = sum2(y0) * P, y1f = sum2(y1) * P;
            y0f += __shfl_xor_sync(0xffffffffu, y0f, 8);
            y1f += __shfl_xor_sync(0xffffffffu, y1f, 8);
            if ((ng & 8) == 0) {
                sYp[tl][pp][ng]      = y0f;
                sYp[tl][pp + 16][ng] = y1f;
            }
        }
        __syncthreads();
        {
            const int t  = tid >> 4;
            const int p0 = (tid & 15) * 2;
            float4 a0 = *(const float4*)&sYp[t][p0][0];
            float4 a1 = *(const float4*)&sYp[t][p0][4];
            float4 b0 = *(const float4*)&sYp[t][p0 + 1][0];
            float4 b1 = *(const float4*)&sYp[t][p0 + 1][4];
            float v0 = (a0.x + a0.y) + (a0.z + a0.w) + (a1.x + a1.y) + (a1.z + a1.w);
            float v1 = (b0.x + b0.y) + (b0.z + b0.w) + (b1.x + b1.y) + (b1.z + b1.w);
            float2* dst = (float2*)&g_y[(size_t)(b * L_ + 512 + kt * 16 + t) * DI + h * HD + pstart + p0];
            const float2 o = *dst;
            *dst = make_float2(o.x + v0, o.y + v1);
        }
        __syncthreads();
    }
}

// ---------------- epilogue ----------------
__global__ __launch_bounds__(256) void epi_kernel(const float* __restrict__ Dp)
{
    const int idx = blockIdx.x * 256 + threadIdx.x;
    const int bt = idx >> 11;
    const int c  = idx & 2047;
    const int h  = c >> 6;
    float y = g_y[idx];
    float x = g_proj[(size_t)bt * DP + DI + c];
    float z = g_proj[(size_t)bt * DP + c];
    float sil = z / (1.f + expf(-z));
    float v = (y + Dp[h] * x) * sil;
    __nv_bfloat16 hh = __float2bfloat16(v);
    __nv_bfloat16 ll = __float2bfloat16(v - __bfloat162float(hh));
    const size_t rb = (size_t)bt * K2X;
    g_y2[rb + c]          = hh;
    g_y2[rb + DI + c]     = ll;
    g_y2[rb + 2 * DI + c] = hh;
}

// ---------------- launch ----------------
extern "C" void kernel_launch(void* const* d_in, const int* in_sizes, int n_in,
                              void* d_out, int out_size)
{
    (void)in_sizes; (void)n_in; (void)out_size;
    const float* u        = (const float*)d_in[0];
    const float* W_in     = (const float*)d_in[1];
    const float* W_out    = (const float*)d_in[2];
    const float* dt_bias  = (const float*)d_in[3];
    const float* B_bias   = (const float*)d_in[4];
    const float* C_bias   = (const float*)d_in[5];
    const float* B_norm_w = (const float*)d_in[6];
    const float* C_norm_w = (const float*)d_in[7];
    const float* D_param  = (const float*)d_in[8];
    float* out = (float*)d_out;

    void *p_proj, *p_u2, *p_wi2, *p_y2, *p_wo2;
    cudaGetSymbolAddress(&p_proj, g_proj);
    cudaGetSymbolAddress(&p_u2,  g_u2);
    cudaGetSymbolAddress(&p_wi2, g_Wi2);
    cudaGetSymbolAddress(&p_y2,  g_y2);
    cudaGetSymbolAddress(&p_wo2, g_Wo2);

    cudaFuncSetAttribute(gemm_bf16, cudaFuncAttributeMaxDynamicSharedMemorySize, GS_TOTAL);
    cudaFuncSetAttribute(scan_kernel, cudaFuncAttributeMaxDynamicSharedMemorySize, SCAN_SMEM_BYTES);

    // 0) folded bf16 splits
    split_A<<<(BT * DM / 4 + 255) / 256, 256>>>(u,     (__nv_bfloat16*)p_u2,  DM / 4, BT * DM / 4);
    split_B<<<(DP * DM / 4 + 255) / 256, 256>>>(W_in,  (__nv_bfloat16*)p_wi2, DM / 4, DP * DM / 4);
    split_B<<<(DM * DI / 4 + 255) / 256, 256>>>(W_out, (__nv_bfloat16*)p_wo2, DI / 4, DM * DI / 4);

    // 1) proj = u @ W_in^T
    gemm_bf16<<<dim3(DP / 128, BT / 128), 256, GS_TOTAL>>>(
        (const __nv_bfloat16*)p_u2, (const __nv_bfloat16*)p_wi2,
        (float*)p_proj, BT, DP, K1X);

    // 2) rmsnorm + head scalars
    prep_kernel<<<BT, 128>>>(dt_bias, B_norm_w, C_norm_w);

    // 3) theta: parallel chunked cumsum + sincos
    thetaA_kernel<<<dim3(32, B_), 1024>>>();
    thetaB_kernel<<<B_, 1024>>>();
    thetaC_kernel<<<dim3(32, B_), 1024>>>();

    // 4) chunked scan (2 L-chunks in parallel) + linear correction
    scan_kernel<<<dim3(4, NH, B_), 256, SCAN_SMEM_BYTES>>>(B_bias, C_bias);
    correct_kernel<<<dim3(2, NH, B_), 256>>>();

    // 5) gated epilogue
    epi_kernel<<<(BT * DI) / 256, 256>>>(D_param);

    // 6) out = yact @ W_out^T
    gemm_bf16<<<dim3(DM / 128, BT / 128), 256, GS_TOTAL>>>(
        (const __nv_bfloat16*)p_y2, (const __nv_bfloat16*)p_wo2,
        out, BT, DM, K2X);
}

// round 14
// speedup vs baseline: 1.2149x; 1.0244x over previous
#include <cuda_runtime.h>
#include <cuda_bf16.h>
#include <math.h>
#include <stdint.h>

#define B_  2
#define L_  1024
#define DM  1024
#define DI  2048
#define NH  32
#define HD  64
#define DS  128
#define NA  32
#define DP  4480   // 2*DI + 2*DS + 3*NH + NA
#define BT  (B_*L_)

#define K1X (3*DM)
#define K2X (3*DI)

typedef unsigned long long ull;

// ---------------- device scratch ----------------
__device__ float g_proj[(size_t)BT * DP];
__device__ float g_Bn  [BT * DS];
__device__ float g_Cn  [BT * DS];
__device__ float g_dt  [BT * NH];
__device__ float g_gd  [BT * NH];
__device__ float g_lam [BT * NH];
__device__ float g_y   [(size_t)BT * DI];
__device__ float g_cos [BT * NH * NA];
__device__ float g_sin [BT * NH * NA];
__device__ float g_csum[B_ * 32 * NH * NA];
__device__ float g_cpre[B_ * 32 * NH * NA];
__device__ float g_Ct  [(size_t)B_ * NH * 512 * 128];    // chunk-1 roped C (16.8 MB)
__device__ ull   g_hend[(size_t)B_ * NH * 256 * 16];     // chunk-0 end state (4 MB)

__device__ __nv_bfloat16 g_u2 [(size_t)BT * K1X];
__device__ __nv_bfloat16 g_Wi2[(size_t)DP * K1X];
__device__ __nv_bfloat16 g_y2 [(size_t)BT * K2X];
__device__ __nv_bfloat16 g_Wo2[(size_t)DM * K2X];

__device__ __forceinline__ float softplusf(float x) {
    return (x > 20.f) ? x : log1pf(expf(x));
}
__device__ __forceinline__ uint32_t smem_u32(const void* p) {
    uint32_t a;
    asm("{ .reg .u64 t; cvta.to.shared.u64 t, %1; cvt.u32.u64 %0, t; }" : "=r"(a) : "l"(p));
    return a;
}

// ---- packed f32x2 helpers ----
__device__ __forceinline__ ull pk2(float v) {
    ull r; asm("mov.b64 %0, {%1, %1};" : "=l"(r) : "f"(v)); return r;
}
__device__ __forceinline__ ull pk2two(float lo, float hi) {
    ull r; asm("mov.b64 %0, {%1, %2};" : "=l"(r) : "f"(lo), "f"(hi)); return r;
}
__device__ __forceinline__ ull fma2(ull a, ull b, ull c) {
    ull d; asm("fma.rn.f32x2 %0, %1, %2, %3;" : "=l"(d) : "l"(a), "l"(b), "l"(c)); return d;
}
__device__ __forceinline__ ull mul2(ull a, ull b) {
    ull d; asm("mul.rn.f32x2 %0, %1, %2;" : "=l"(d) : "l"(a), "l"(b)); return d;
}
__device__ __forceinline__ float sum2(ull a) {
    float x, y;
    asm("mov.b64 {%0, %1}, %2;" : "=f"(x), "=f"(y) : "l"(a));
    return x + y;
}

#define CP_ASYNC16(dst, src) \
    asm volatile("cp.async.cg.shared.global [%0], [%1], 16;" :: "r"(dst), "l"(src))
#define CP_ASYNC4(dst, src) \
    asm volatile("cp.async.ca.shared.global [%0], [%1], 4;" :: "r"(dst), "l"(src))
#define CP_COMMIT() asm volatile("cp.async.commit_group;")
#define CP_WAIT1()  asm volatile("cp.async.wait_group 1;")
#define CP_WAIT0()  asm volatile("cp.async.wait_group 0;")

__device__ __forceinline__ void ldsm_x4(uint32_t* r, uint32_t addr) {
    asm volatile("ldmatrix.sync.aligned.m8n8.x4.shared.b16 {%0,%1,%2,%3}, [%4];"
        : "=r"(r[0]), "=r"(r[1]), "=r"(r[2]), "=r"(r[3]) : "r"(addr));
}
__device__ __forceinline__ void mma16816(float* d, const uint32_t* a, const uint32_t* b) {
    asm volatile(
        "mma.sync.aligned.m16n8k16.row.col.f32.bf16.bf16.f32 "
        "{%0,%1,%2,%3},{%4,%5,%6,%7},{%8,%9},{%0,%1,%2,%3};"
        : "+f"(d[0]), "+f"(d[1]), "+f"(d[2]), "+f"(d[3])
        : "r"(a[0]), "r"(a[1]), "r"(a[2]), "r"(a[3]), "r"(b[0]), "r"(b[1]));
}

// ---------------- split kernels ----------------
__global__ __launch_bounds__(256) void split_A(
    const float* __restrict__ src, __nv_bfloat16* __restrict__ dst, int Kq, int n4)
{
    int i = blockIdx.x * 256 + threadIdx.x;
    if (i >= n4) return;
    int row = i / Kq, k4 = (i - row * Kq) * 4;
    float4 v = *(const float4*)(src + (size_t)row * (Kq * 4) + k4);
    __nv_bfloat162 h01 = __floats2bfloat162_rn(v.x, v.y);
    __nv_bfloat162 h23 = __floats2bfloat162_rn(v.z, v.w);
    __nv_bfloat162 l01 = __floats2bfloat162_rn(v.x - __low2float(h01), v.y - __high2float(h01));
    __nv_bfloat162 l23 = __floats2bfloat162_rn(v.z - __low2float(h23), v.w - __high2float(h23));
    const int K = Kq * 4;
    __nv_bfloat162* d0 = (__nv_bfloat162*)(dst + (size_t)row * 3 * K + k4);
    __nv_bfloat162* d1 = (__nv_bfloat162*)(dst + (size_t)row * 3 * K + K + k4);
    __nv_bfloat162* d2 = (__nv_bfloat162*)(dst + (size_t)row * 3 * K + 2 * K + k4);
    d0[0] = h01; d0[1] = h23;
    d1[0] = l01; d1[1] = l23;
    d2[0] = h01; d2[1] = h23;
}
__global__ __launch_bounds__(256) void split_B(
    const float* __restrict__ src, __nv_bfloat16* __restrict__ dst, int Kq, int n4)
{
    int i = blockIdx.x * 256 + threadIdx.x;
    if (i >= n4) return;
    int row = i / Kq, k4 = (i - row * Kq) * 4;
    float4 v = *(const float4*)(src + (size_t)row * (Kq * 4) + k4);
    __nv_bfloat162 h01 = __floats2bfloat162_rn(v.x, v.y);
    __nv_bfloat162 h23 = __floats2bfloat162_rn(v.z, v.w);
    __nv_bfloat162 l01 = __floats2bfloat162_rn(v.x - __low2float(h01), v.y - __high2float(h01));
    __nv_bfloat162 l23 = __floats2bfloat162_rn(v.z - __low2float(h23), v.w - __high2float(h23));
    const int K = Kq * 4;
    __nv_bfloat162* d0 = (__nv_bfloat162*)(dst + (size_t)row * 3 * K + k4);
    __nv_bfloat162* d1 = (__nv_bfloat162*)(dst + (size_t)row * 3 * K + K + k4);
    __nv_bfloat162* d2 = (__nv_bfloat162*)(dst + (size_t)row * 3 * K + 2 * K + k4);
    d0[0] = h01; d0[1] = h23;
    d1[0] = h01; d1[1] = h23;
    d2[0] = l01; d2[1] = l23;
}

// ---------------- bf16 mma.sync GEMM (R8 2-stage, unchanged) ----------------
#define GS_STAGE 32768
#define GS_TOTAL (2 * GS_STAGE + 1024)

__global__ __launch_bounds__(256) void gemm_bf16(
    const __nv_bfloat16* __restrict__ A, const __nv_bfloat16* __restrict__ Bm,
    float* __restrict__ C, int M, int N, int K)
{
    extern __shared__ char dynsmem[];
    const int tid = threadIdx.x;
    const int wid = tid >> 5, lane = tid & 31;
    const int bm = blockIdx.y * 128, bn = blockIdx.x * 128;
    const int m_warp = (wid >> 1) * 32, n_warp = (wid & 1) * 64;

    uint32_t raw = smem_u32(dynsmem);
    const uint32_t sbase = (raw + 1023u) & ~1023u;

    uint32_t psw[4];
    const __nv_bfloat16 *Ap[4], *Bp[4];
#pragma unroll
    for (int i = 0; i < 4; i++) {
        const int chunk = tid + i * 256;
        const int row = chunk >> 3, c = chunk & 7;
        psw[i] = row * 128 + ((c ^ (row & 7)) << 4);
        Ap[i] = A  + (size_t)(bm + row) * K + c * 8;
        Bp[i] = Bm + (size_t)(bn + row) * K + c * 8;
    }

    const int khA = lane >> 4;
    const int rA0 = m_warp + (lane & 15), rA1 = rA0 + 16;
    const uint32_t offA0 = rA0 * 128, offA1 = rA1 * 128;
    const int x7A0 = rA0 & 7, x7A1 = rA1 & 7;
    const int khB = (lane >> 3) & 1;
    const int rb_off = (lane & 7) + ((lane >> 4) << 3);
    uint32_t offB[4]; int x7B[4];
#pragma unroll
    for (int np = 0; np < 4; np++) {
        const int r = n_warp + np * 16 + rb_off;
        offB[np] = r * 128; x7B[np] = r & 7;
    }

    float acc[2][8][4];
#pragma unroll
    for (int mt = 0; mt < 2; mt++)
#pragma unroll
        for (int nt = 0; nt < 8; nt++)
#pragma unroll
            for (int e = 0; e < 4; e++) acc[mt][nt][e] = 0.f;

    const int nk = K >> 6;
    {
        const uint32_t s = sbase;
#pragma unroll
        for (int i = 0; i < 4; i++) {
            CP_ASYNC16(s + psw[i], Ap[i]);
            CP_ASYNC16(s + 16384 + psw[i], Bp[i]);
        }
        CP_COMMIT();
    }

    for (int kc = 0; kc < nk; kc++) {
        const int buf = kc & 1;
        if (kc + 1 < nk) {
            const uint32_t s = sbase + (buf ^ 1) * GS_STAGE;
            const int ko = (kc + 1) << 6;
#pragma unroll
            for (int i = 0; i < 4; i++) {
                CP_ASYNC16(s + psw[i], Ap[i] + ko);
                CP_ASYNC16(s + 16384 + psw[i], Bp[i] + ko);
            }
            CP_COMMIT();
            CP_WAIT1();
        } else {
            CP_WAIT0();
        }
        __syncthreads();

        const uint32_t sA = sbase + buf * GS_STAGE;
        const uint32_t sB = sA + 16384;
#pragma unroll
        for (int ks = 0; ks < 4; ks++) {
            uint32_t a0[4], a1[4];
            const int cA = 2 * ks + khA;
            ldsm_x4(a0, sA + offA0 + ((cA ^ x7A0) << 4));
            ldsm_x4(a1, sA + offA1 + ((cA ^ x7A1) << 4));
            uint32_t b[8][2];
            const int cB = 2 * ks + khB;
#pragma unroll
            for (int np = 0; np < 4; np++) {
                uint32_t r[4];
                ldsm_x4(r, sB + offB[np] + ((cB ^ x7B[np]) << 4));
                b[2 * np][0] = r[0]; b[2 * np][1] = r[1];
                b[2 * np + 1][0] = r[2]; b[2 * np + 1][1] = r[3];
            }
#pragma unroll
            for (int nt = 0; nt < 8; nt++) {
                mma16816(acc[0][nt], a0, b[nt]);
                mma16816(acc[1][nt], a1, b[nt]);
            }
        }
        __syncthreads();
    }

    const int tr = lane >> 2, tc = (lane & 3) * 2;
#pragma unroll
    for (int mt = 0; mt < 2; mt++) {
        const int row0 = bm + m_warp + mt * 16 + tr;
#pragma unroll
        for (int nt = 0; nt < 8; nt++) {
            const int col = bn + n_warp + nt * 8 + tc;
            *(float2*)(C + (size_t)row0 * N + col)       = make_float2(acc[mt][nt][0], acc[mt][nt][1]);
            *(float2*)(C + (size_t)(row0 + 8) * N + col) = make_float2(acc[mt][nt][2], acc[mt][nt][3]);
        }
    }
}

// ---------------- prep ----------------
__global__ __launch_bounds__(128) void prep_kernel(
    const float* __restrict__ dt_bias,
    const float* __restrict__ Bnw, const float* __restrict__ Cnw)
{
    const int bt = blockIdx.x;
    const int n  = threadIdx.x;
    const size_t base = (size_t)bt * DP;

    float Bv = g_proj[base + 2 * DI + n];
    float Cv = g_proj[base + 2 * DI + DS + n];
    float sb = Bv * Bv, sc = Cv * Cv;
#pragma unroll
    for (int o = 16; o > 0; o >>= 1) {
        sb += __shfl_xor_sync(0xffffffffu, sb, o);
        sc += __shfl_xor_sync(0xffffffffu, sc, o);
    }
    __shared__ float red[2][4];
    const int w = n >> 5, ln = n & 31;
    if (ln == 0) { red[0][w] = sb; red[1][w] = sc; }
    __syncthreads();
    float tb = red[0][0] + red[0][1] + red[0][2] + red[0][3];
    float tc = red[1][0] + red[1][1] + red[1][2] + red[1][3];

    g_Bn[bt * DS + n] = Bv * rsqrtf(tb * (1.f / DS) + 1e-5f) * Bnw[n];
    g_Cn[bt * DS + n] = Cv * rsqrtf(tc * (1.f / DS) + 1e-5f) * Cnw[n];

    if (n < NH) {
        float dd = g_proj[base + 2 * DI + 2 * DS + n];
        float dA = g_proj[base + 2 * DI + 2 * DS + NH + n];
        float tr = g_proj[base + 2 * DI + 2 * DS + 2 * NH + n];
        float dt = softplusf(dd + dt_bias[n]);
        float a  = -softplusf(dA);
        a = fminf(a, -1e-4f);
        g_dt [bt * NH + n] = dt;
        g_gd [bt * NH + n] = expf(a * dt);
        g_lam[bt * NH + n] = 1.f / (1.f + expf(-tr));
    }
}

// ---------------- theta: parallel 3-pass ----------------
__global__ __launch_bounds__(1024) void thetaA_kernel()
{
    const int c = blockIdx.x, b = blockIdx.y;
    __shared__ float sdt[1024], sang[1024];
    const int i = threadIdx.x;
    const int bt0 = b * L_ + c * 32;
    sdt[i] = g_dt[bt0 * NH + i];
    const int s = i >> 5, j = i & 31;
    sang[i] = g_proj[(size_t)(bt0 + s) * DP + (DP - NA) + j];
    __syncthreads();
    const int h = i >> 5;
    float acc = 0.f;
#pragma unroll
    for (int ss = 0; ss < 32; ss++)
        acc = fmaf(sdt[ss * 32 + h], sang[ss * 32 + j], acc);
    g_csum[(b * 32 + c) * 1024 + i] = acc;
}

__global__ __launch_bounds__(1024) void thetaB_kernel()
{
    const int b = blockIdx.x, i = threadIdx.x;
    float run = 0.f;
    for (int c = 0; c < 32; c++) {
        float v = g_csum[(b * 32 + c) * 1024 + i];
        g_cpre[(b * 32 + c) * 1024 + i] = run;
        run += v;
    }
}

__global__ __launch_bounds__(1024) void thetaC_kernel()
{
    const int c = blockIdx.x, b = blockIdx.y;
    __shared__ float sdt[1024], sang[1024];
    const int i = threadIdx.x;
    const int bt0 = b * L_ + c * 32;
    sdt[i] = g_dt[bt0 * NH + i];
    const int s0 = i >> 5, j = i & 31;
    sang[i] = g_proj[(size_t)(bt0 + s0) * DP + (DP - NA) + j];
    __syncthreads();
    const int h = i >> 5;
    float run = g_cpre[(b * 32 + c) * 1024 + i];
#pragma unroll
    for (int s = 0; s < 32; s++) {
        run = fmaf(sdt[s * 32 + h], sang[s * 32 + j], run);
        float sn, cs;
        __sincosf(run, &sn, &cs);
        const int o = (bt0 + s) * 1024 + i;
        g_cos[o] = cs;
        g_sin[o] = sn;
    }
}

// ---------------- chunked scan: 128 CTAs (1/SM), full p=64 per CTA ----------------
// blockIdx.x = chunk (0,1). Thread: pp = tid>>4 -> p rows {pp, pp+16, pp+32, pp+48};
// ng = tid&15 -> n [ng*8, +8) as 4 f32x2. Chunk 1: h_in=0 (corrected), exact bx_prev.
#define ST 16
#define NTILE (L_ / ST)
#define HTILE (NTILE / 2)

struct __align__(16) ScanSmem {
    float sB[2][ST][128];     // 16 KB
    float sC[2][ST][128];     // 16 KB
    float sCs[2][ST][32];     // 4 KB
    float sSn[2][ST][32];     // 4 KB
    float sX[2][ST][64];      // 8 KB
    float sScal[2][3][ST];
    float sYp[ST][64][8];     // 32 KB
};
#define SCAN_SMEM_BYTES ((int)sizeof(ScanSmem))

__global__ __launch_bounds__(256) void scan_kernel(
    const float* __restrict__ Bbias, const float* __restrict__ Cbias)
{
    extern __shared__ char dynsmem[];
    ScanSmem* s = (ScanSmem*)dynsmem;

    const int chunk = blockIdx.x;
    const int h = blockIdx.y;
    const int b = blockIdx.z;
    const int tid = threadIdx.x;
    const int pp = tid >> 4;         // 0..15
    const int ng = tid & 15;
    const int n0 = ng * 8;
    const int K0 = chunk * HTILE;

    const int nn = tid & 63;
    const int tq = (tid >> 6) & 1;
    const float* biasPtr = (tid < 128) ? Bbias : Cbias;
    float ba1, ba2;
    if (nn < 32) { ba1 = biasPtr[h * DS + nn];      ba2 = biasPtr[h * DS + nn + 32]; }
    else         { ba1 = biasPtr[h * DS + nn + 32]; ba2 = biasPtr[h * DS + nn + 64]; }

#define PREFETCH(k, pbuf) do {                                                   \
        const int bt0_ = b * L_ + (k) * ST;                                      \
        _Pragma("unroll")                                                        \
        for (int r = 0; r < 2; r++) {                                            \
            const int q = tid + r * 256, tp = q >> 5, seg = q & 31;              \
            CP_ASYNC16(smem_u32(&s->sB[pbuf][tp][seg * 4]),                      \
                       &g_Bn[(bt0_ + tp) * DS + seg * 4]);                       \
            CP_ASYNC16(smem_u32(&s->sC[pbuf][tp][seg * 4]),                      \
                       &g_Cn[(bt0_ + tp) * DS + seg * 4]);                       \
        }                                                                        \
        {                                                                        \
            const int tp = tid >> 4, seg = tid & 15;                             \
            CP_ASYNC16(smem_u32(&s->sX[pbuf][tp][seg * 4]),                      \
                       &g_proj[(size_t)(bt0_ + tp) * DP + DI + h * HD + seg * 4]); \
        }                                                                        \
        if (tid < 128) {                                                         \
            const int tp = tid >> 3, seg = tid & 7;                              \
            CP_ASYNC16(smem_u32(&s->sCs[pbuf][tp][seg * 4]),                     \
                       &g_cos[((bt0_ + tp) * NH + h) * NA + seg * 4]);           \
            CP_ASYNC16(smem_u32(&s->sSn[pbuf][tp][seg * 4]),                     \
                       &g_sin[((bt0_ + tp) * NH + h) * NA + seg * 4]);           \
        }                                                                        \
        if (tid < 48) {                                                          \
            const int which = tid >> 4, tp = tid & 15;                           \
            const float* srcs = (which == 0) ? g_dt : (which == 1) ? g_gd : g_lam; \
            CP_ASYNC4(smem_u32(&s->sScal[pbuf][which][tp]),                      \
                      &srcs[(bt0_ + tp) * NH + h]);                              \
        }                                                                        \
        CP_COMMIT();                                                             \
    } while (0)

    ull hq[4][4], Bp[4];
#pragma unroll
    for (int q = 0; q < 4; q++)
#pragma unroll
        for (int j = 0; j < 4; j++) hq[q][j] = 0ull;
#pragma unroll
    for (int j = 0; j < 4; j++) Bp[j] = 0ull;
    float xp[4] = {0.f, 0.f, 0.f, 0.f};

    // Chunk-1: exact bx_prev init from t = 511 (h_in stays 0; corrected later).
    if (chunk == 1) {
        const int bt511 = b * L_ + (L_ / 2 - 1);
#pragma unroll
        for (int q = 0; q < 4; q++)
            xp[q] = g_proj[(size_t)bt511 * DP + DI + h * HD + pp + 16 * q];
        float bq[8];
#pragma unroll
        for (int i = 0; i < 8; i++) {
            const int n = n0 + i;
            float v;
            if (n < 32) {
                const float cn = g_cos[(bt511 * NH + h) * NA + n];
                const float sn = g_sin[(bt511 * NH + h) * NA + n];
                const float v1 = g_Bn[bt511 * DS + n]      + Bbias[h * DS + n];
                const float v2 = g_Bn[bt511 * DS + n + 32] + Bbias[h * DS + n + 32];
                v = v1 * cn - v2 * sn;
            } else if (n < 64) {
                const int j = n - 32;
                const float cn = g_cos[(bt511 * NH + h) * NA + j];
                const float sn = g_sin[(bt511 * NH + h) * NA + j];
                const float v1 = g_Bn[bt511 * DS + j] + Bbias[h * DS + j];
                const float v2 = g_Bn[bt511 * DS + n] + Bbias[h * DS + n];
                v = v1 * sn + v2 * cn;
            } else {
                v = g_Bn[bt511 * DS + n] + Bbias[h * DS + n];
            }
            bq[i] = v;
        }
        Bp[0] = pk2two(bq[0], bq[1]); Bp[1] = pk2two(bq[2], bq[3]);
        Bp[2] = pk2two(bq[4], bq[5]); Bp[3] = pk2two(bq[6], bq[7]);
    }

    PREFETCH(K0, 0);

    for (int kk = 0; kk < HTILE; kk++) {
        const int k = K0 + kk;
        const int buf = kk & 1;
        if (kk + 1 < HTILE) {
            PREFETCH(k + 1, buf ^ 1);
            CP_WAIT1();
        } else {
            CP_WAIT0();
        }
        __syncthreads();

        // ---- bias + RoPE stage ----
        {
            float* mat = (tid < 128) ? &s->sB[buf][0][0] : &s->sC[buf][0][0];
#pragma unroll
            for (int tp = tq; tp < ST; tp += 2) {
                float* rb = mat + tp * 128;
                if (nn < 32) {
                    const float cv = s->sCs[buf][tp][nn], sv = s->sSn[buf][tp][nn];
                    const float v1 = rb[nn] + ba1, v2 = rb[nn + 32] + ba2;
                    rb[nn]      = v1 * cv - v2 * sv;
                    rb[nn + 32] = v1 * sv + v2 * cv;
                } else {
                    rb[nn + 32] += ba1;
                    rb[nn + 64] += ba2;
                }
            }
        }
        __syncthreads();

        // chunk-1 persists roped C for the correction pass
        if (chunk == 1) {
            const int tl = tid >> 4, nc = (tid & 15) * 8;
            const size_t cb = ((size_t)(b * NH + h) * 512 + (k - HTILE) * ST + tl) * 128 + nc;
            *(float4*)&g_Ct[cb]     = *(const float4*)&s->sC[buf][tl][nc];
            *(float4*)&g_Ct[cb + 4] = *(const float4*)&s->sC[buf][tl][nc + 4];
        }

        // ---- 16 timesteps ----
#pragma unroll
        for (int tp = 0; tp < ST; tp++) {
            const float dt  = s->sScal[buf][0][tp];
            const float g   = s->sScal[buf][1][tp];
            const float lam = s->sScal[buf][2][tp];
            const float k1 = dt * lam;
            const float k2 = dt * (1.f - lam) * g;
            const ull g2 = pk2(g);

            const ulonglong2 b01 = *(const ulonglong2*)&s->sB[buf][tp][n0];
            const ulonglong2 b23 = *(const ulonglong2*)&s->sB[buf][tp][n0 + 4];
            const ulonglong2 c01 = *(const ulonglong2*)&s->sC[buf][tp][n0];
            const ulonglong2 c23 = *(const ulonglong2*)&s->sC[buf][tp][n0 + 4];
            const ull bv[4] = { b01.x, b01.y, b23.x, b23.y };
            const ull cv[4] = { c01.x, c01.y, c23.x, c23.y };

            float yf[4];
#pragma unroll
            for (int q = 0; q < 4; q++) {
                const float xc = s->sX[buf][tp][pp + 16 * q];
                const ull c1 = pk2(k1 * xc);
                const ull c2 = pk2(k2 * xp[q]);
                ull y = 0ull;
#pragma unroll
                for (int j = 0; j < 4; j++) {
                    ull t0 = mul2(c2, Bp[j]);
                    t0 = fma2(c1, bv[j], t0);
                    hq[q][j] = fma2(g2, hq[q][j], t0);
                    y = fma2(hq[q][j], cv[j], y);
                }
                xp[q] = xc;
                yf[q] = sum2(y);
            }
#pragma unroll
            for (int j = 0; j < 4; j++) Bp[j] = bv[j];

#pragma unroll
            for (int q = 0; q < 4; q++)
                yf[q] += __shfl_xor_sync(0xffffffffu, yf[q], 8);
            if ((ng & 8) == 0) {
#pragma unroll
                for (int q = 0; q < 4; q++)
                    s->sYp[tp][pp + 16 * q][ng] = yf[q];
            }
        }
        __syncthreads();

        // ---- batched per-tile reduce: 1024 (t,p) pairs, 4 per thread ----
#pragma unroll
        for (int r = 0; r < 4; r++) {
            const int idx = tid + r * 256;
            const int t  = idx >> 6;        // 0..15
            const int p0 = idx & 63;        // 0..63
            float4 a0 = *(const float4*)&s->sYp[t][p0][0];
            float4 a1 = *(const float4*)&s->sYp[t][p0][4];
            float v0 = (a0.x + a0.y) + (a0.z + a0.w) + (a1.x + a1.y) + (a1.z + a1.w);
            g_y[(size_t)(b * L_ + k * ST + t) * DI + h * HD + p0] = v0;
        }
        __syncthreads();
    }
#undef PREFETCH

    // chunk-0 publishes its end state (h at t = 511)
    if (chunk == 0) {
        ull* hd = g_hend + ((size_t)((b * NH + h)) * 256 + tid) * 16;
#pragma unroll
        for (int q = 0; q < 4; q++)
#pragma unroll
            for (int j = 0; j < 4; j++) hd[q * 4 + j] = hq[q][j];
    }
}

// ---------------- correction: y_t += P_t * (C~_t . h_in), t in [512, 1024) ----------------
__global__ __launch_bounds__(256) void correct_kernel()
{
    const int h = blockIdx.x;
    const int b = blockIdx.y;
    const int tid = threadIdx.x;
    const int pp = tid >> 4;
    const int ng = tid & 15;
    const int n0 = ng * 8;

    __shared__ float sGd[512];
    __shared__ float sYp[16][64][8];

    const ull* hd = g_hend + ((size_t)(b * NH + h) * 256 + tid) * 16;
    ull hq[4][4];
#pragma unroll
    for (int q = 0; q < 4; q++)
#pragma unroll
        for (int j = 0; j < 4; j++) hq[q][j] = hd[q * 4 + j];

    for (int i = tid; i < 512; i += 256)
        sGd[i] = g_gd[(b * L_ + 512 + i) * NH + h];
    __syncthreads();

    float P = 1.f;
    for (int kt = 0; kt < 32; kt++) {
#pragma unroll
        for (int tl = 0; tl < 16; tl++) {
            const int ti = kt * 16 + tl;
            P *= sGd[ti];
            const size_t cb = ((size_t)(b * NH + h) * 512 + ti) * 128 + n0;
            const ulonglong2 cc0 = *(const ulonglong2*)&g_Ct[cb];
            const ulonglong2 cc1 = *(const ulonglong2*)&g_Ct[cb + 4];
            const ull cv[4] = { cc0.x, cc0.y, cc1.x, cc1.y };
            float yf[4];
#pragma unroll
            for (int q = 0; q < 4; q++) {
                ull y = 0ull;
#pragma unroll
                for (int j = 0; j < 4; j++)
                    y = fma2(hq[q][j], cv[j], y);
                yf[q] = sum2(y) * P;
            }
#pragma unroll
            for (int q = 0; q < 4; q++)
                yf[q] += __shfl_xor_sync(0xffffffffu, yf[q], 8);
            if ((ng & 8) == 0) {
#pragma unroll
                for (int q = 0; q < 4; q++)
                    sYp[tl][pp + 16 * q][ng] = yf[q];
            }
        }
        __syncthreads();
#pragma unroll
        for (int r = 0; r < 4; r++) {
            const int idx = tid + r * 256;
            const int t  = idx >> 6;
            const int p0 = idx & 63;
            float4 a0 = *(const float4*)&sYp[t][p0][0];
            float4 a1 = *(const float4*)&sYp[t][p0][4];
            float v0 = (a0.x + a0.y) + (a0.z + a0.w) + (a1.x + a1.y) + (a1.z + a1.w);
            g_y[(size_t)(b * L_ + 512 + kt * 16 + t) * DI + h * HD + p0] += v0;
        }
        __syncthreads();
    }
}

// ---------------- epilogue ----------------
__global__ __launch_bounds__(256) void epi_kernel(const float* __restrict__ Dp)
{
    const int idx = blockIdx.x * 256 + threadIdx.x;
    const int bt = idx >> 11;
    const int c  = idx & 2047;
    const int h  = c >> 6;
    float y = g_y[idx];
    float x = g_proj[(size_t)bt * DP + DI + c];
    float z = g_proj[(size_t)bt * DP + c];
    float sil = z / (1.f + expf(-z));
    float v = (y + Dp[h] * x) * sil;
    __nv_bfloat16 hh = __float2bfloat16(v);
    __nv_bfloat16 ll = __float2bfloat16(v - __bfloat162float(hh));
    const size_t rb = (size_t)bt * K2X;
    g_y2[rb + c]          = hh;
    g_y2[rb + DI + c]     = ll;
    g_y2[rb + 2 * DI + c] = hh;
}

// ---------------- launch ----------------
extern "C" void kernel_launch(void* const* d_in, const int* in_sizes, int n_in,
                              void* d_out, int out_size)
{
    (void)in_sizes; (void)n_in; (void)out_size;
    const float* u        = (const float*)d_in[0];
    const float* W_in     = (const float*)d_in[1];
    const float* W_out    = (const float*)d_in[2];
    const float* dt_bias  = (const float*)d_in[3];
    const float* B_bias   = (const float*)d_in[4];
    const float* C_bias   = (const float*)d_in[5];
    const float* B_norm_w = (const float*)d_in[6];
    const float* C_norm_w = (const float*)d_in[7];
    const float* D_param  = (const float*)d_in[8];
    float* out = (float*)d_out;

    void *p_proj, *p_u2, *p_wi2, *p_y2, *p_wo2;
    cudaGetSymbolAddress(&p_proj, g_proj);
    cudaGetSymbolAddress(&p_u2,  g_u2);
    cudaGetSymbolAddress(&p_wi2, g_Wi2);
    cudaGetSymbolAddress(&p_y2,  g_y2);
    cudaGetSymbolAddress(&p_wo2, g_Wo2);

    cudaFuncSetAttribute(gemm_bf16, cudaFuncAttributeMaxDynamicSharedMemorySize, GS_TOTAL);
    cudaFuncSetAttribute(scan_kernel, cudaFuncAttributeMaxDynamicSharedMemorySize, SCAN_SMEM_BYTES);

    // 0) folded bf16 splits
    split_A<<<(BT * DM / 4 + 255) / 256, 256>>>(u,     (__nv_bfloat16*)p_u2,  DM / 4, BT * DM / 4);
    split_B<<<(DP * DM / 4 + 255) / 256, 256>>>(W_in,  (__nv_bfloat16*)p_wi2, DM / 4, DP * DM / 4);
    split_B<<<(DM * DI / 4 + 255) / 256, 256>>>(W_out, (__nv_bfloat16*)p_wo2, DI / 4, DM * DI / 4);

    // 1) proj = u @ W_in^T
    gemm_bf16<<<dim3(DP / 128, BT / 128), 256, GS_TOTAL>>>(
        (const __nv_bfloat16*)p_u2, (const __nv_bfloat16*)p_wi2,
        (float*)p_proj, BT, DP, K1X);

    // 2) rmsnorm + head scalars
    prep_kernel<<<BT, 128>>>(dt_bias, B_norm_w, C_norm_w);

    // 3) theta: parallel chunked cumsum + sincos
    thetaA_kernel<<<dim3(32, B_), 1024>>>();
    thetaB_kernel<<<B_, 1024>>>();
    thetaC_kernel<<<dim3(32, B_), 1024>>>();

    // 4) chunked scan (128 CTAs, 1/SM) + linear correction
    scan_kernel<<<dim3(2, NH, B_), 256, SCAN_SMEM_BYTES>>>(B_bias, C_bias);
    correct_kernel<<<dim3(NH, B_), 256>>>();

    // 5) gated epilogue
    epi_kernel<<<(BT * DI) / 256, 256>>>(D_param);

    // 6) out = yact @ W_out^T
    gemm_bf16<<<dim3(DM / 128, BT / 128), 256, GS_TOTAL>>>(
        (const __nv_bfloat16*)p_y2, (const __nv_bfloat16*)p_wo2,
        out, BT, DM, K2X);
}

// round 16
// speedup vs baseline: 1.4261x; 1.1738x over previous
#include <cuda_runtime.h>
#include <cuda_bf16.h>
#include <math.h>
#include <stdint.h>

#define B_  2
#define L_  1024
#define DM  1024
#define DI  2048
#define NH  32
#define HD  64
#define DS  128
#define NA  32
#define DP  4480   // 2*DI + 2*DS + 3*NH + NA
#define BT  (B_*L_)

#define K1X (3*DM)      // gemm1 folded K' = 3072
#define K2X (3*DI)      // gemm2 folded K' = 6144

// ---------------- device scratch ----------------
__device__ float g_proj[(size_t)BT * DP];
__device__ float g_Bn  [BT * DS];
__device__ float g_Cn  [BT * DS];
__device__ float g_dt  [BT * NH];
__device__ float g_gd  [BT * NH];
__device__ float g_lam [BT * NH];
__device__ float g_cos [BT * NH * NA];
__device__ float g_sin [BT * NH * NA];
__device__ float g_y   [(size_t)BT * DI];
__device__ float g_csum[B_ * 32 * NH * NA];
__device__ float g_cpre[B_ * 32 * NH * NA];

__device__ __nv_bfloat16 g_u2 [(size_t)BT * K1X];
__device__ __nv_bfloat16 g_Wi2[(size_t)DP * K1X];
__device__ __nv_bfloat16 g_y2 [(size_t)BT * K2X];
__device__ __nv_bfloat16 g_Wo2[(size_t)DM * K2X];

typedef unsigned long long ull;

__device__ __forceinline__ float softplusf(float x) {
    return (x > 20.f) ? x : log1pf(expf(x));
}
__device__ __forceinline__ uint32_t smem_u32(const void* p) {
    uint32_t a;
    asm("{ .reg .u64 t; cvta.to.shared.u64 t, %1; cvt.u32.u64 %0, t; }" : "=r"(a) : "l"(p));
    return a;
}

// ---- packed f32x2 helpers ----
__device__ __forceinline__ ull pk2(float v) {
    ull r; asm("mov.b64 %0, {%1, %1};" : "=l"(r) : "f"(v)); return r;
}
__device__ __forceinline__ ull fma2(ull a, ull b, ull c) {
    ull d; asm("fma.rn.f32x2 %0, %1, %2, %3;" : "=l"(d) : "l"(a), "l"(b), "l"(c)); return d;
}
__device__ __forceinline__ ull mul2(ull a, ull b) {
    ull d; asm("mul.rn.f32x2 %0, %1, %2;" : "=l"(d) : "l"(a), "l"(b)); return d;
}
__device__ __forceinline__ float sum2(ull a) {
    float x, y;
    asm("mov.b64 {%0, %1}, %2;" : "=f"(x), "=f"(y) : "l"(a));
    return x + y;
}

#define CP_ASYNC16(dst, src) \
    asm volatile("cp.async.cg.shared.global [%0], [%1], 16;" :: "r"(dst), "l"(src))
#define CP_ASYNC4(dst, src) \
    asm volatile("cp.async.ca.shared.global [%0], [%1], 4;" :: "r"(dst), "l"(src))
#define CP_COMMIT() asm volatile("cp.async.commit_group;")
#define CP_WAIT1()  asm volatile("cp.async.wait_group 1;")
#define CP_WAIT0()  asm volatile("cp.async.wait_group 0;")

__device__ __forceinline__ void ldsm_x4(uint32_t* r, uint32_t addr) {
    asm volatile("ldmatrix.sync.aligned.m8n8.x4.shared.b16 {%0,%1,%2,%3}, [%4];"
        : "=r"(r[0]), "=r"(r[1]), "=r"(r[2]), "=r"(r[3]) : "r"(addr));
}
__device__ __forceinline__ void mma16816(float* d, const uint32_t* a, const uint32_t* b) {
    asm volatile(
        "mma.sync.aligned.m16n8k16.row.col.f32.bf16.bf16.f32 "
        "{%0,%1,%2,%3},{%4,%5,%6,%7},{%8,%9},{%0,%1,%2,%3};"
        : "+f"(d[0]), "+f"(d[1]), "+f"(d[2]), "+f"(d[3])
        : "r"(a[0]), "r"(a[1]), "r"(a[2]), "r"(a[3]), "r"(b[0]), "r"(b[1]));
}

// ---------------- split kernels ----------------
__global__ __launch_bounds__(256) void split_A(
    const float* __restrict__ src, __nv_bfloat16* __restrict__ dst, int Kq, int n4)
{
    int i = blockIdx.x * 256 + threadIdx.x;
    if (i >= n4) return;
    int row = i / Kq, k4 = (i - row * Kq) * 4;
    float4 v = *(const float4*)(src + (size_t)row * (Kq * 4) + k4);
    __nv_bfloat162 h01 = __floats2bfloat162_rn(v.x, v.y);
    __nv_bfloat162 h23 = __floats2bfloat162_rn(v.z, v.w);
    __nv_bfloat162 l01 = __floats2bfloat162_rn(v.x - __low2float(h01), v.y - __high2float(h01));
    __nv_bfloat162 l23 = __floats2bfloat162_rn(v.z - __low2float(h23), v.w - __high2float(h23));
    const int K = Kq * 4;
    __nv_bfloat162* d0 = (__nv_bfloat162*)(dst + (size_t)row * 3 * K + k4);
    __nv_bfloat162* d1 = (__nv_bfloat162*)(dst + (size_t)row * 3 * K + K + k4);
    __nv_bfloat162* d2 = (__nv_bfloat162*)(dst + (size_t)row * 3 * K + 2 * K + k4);
    d0[0] = h01; d0[1] = h23;
    d1[0] = l01; d1[1] = l23;
    d2[0] = h01; d2[1] = h23;
}
__global__ __launch_bounds__(256) void split_B(
    const float* __restrict__ src, __nv_bfloat16* __restrict__ dst, int Kq, int n4)
{
    int i = blockIdx.x * 256 + threadIdx.x;
    if (i >= n4) return;
    int row = i / Kq, k4 = (i - row * Kq) * 4;
    float4 v = *(const float4*)(src + (size_t)row * (Kq * 4) + k4);
    __nv_bfloat162 h01 = __floats2bfloat162_rn(v.x, v.y);
    __nv_bfloat162 h23 = __floats2bfloat162_rn(v.z, v.w);
    __nv_bfloat162 l01 = __floats2bfloat162_rn(v.x - __low2float(h01), v.y - __high2float(h01));
    __nv_bfloat162 l23 = __floats2bfloat162_rn(v.z - __low2float(h23), v.w - __high2float(h23));
    const int K = Kq * 4;
    __nv_bfloat162* d0 = (__nv_bfloat162*)(dst + (size_t)row * 3 * K + k4);
    __nv_bfloat162* d1 = (__nv_bfloat162*)(dst + (size_t)row * 3 * K + K + k4);
    __nv_bfloat162* d2 = (__nv_bfloat162*)(dst + (size_t)row * 3 * K + 2 * K + k4);
    d0[0] = h01; d0[1] = h23;
    d1[0] = h01; d1[1] = h23;
    d2[0] = l01; d2[1] = l23;
}

// ---------------- bf16 mma.sync GEMM, templated CTA tile 128xBN ----------------
// BN=128 instantiation is identical to the proven R8 kernel.
template<int BN>
__global__ __launch_bounds__(256) void gemm_bf16(
    const __nv_bfloat16* __restrict__ A, const __nv_bfloat16* __restrict__ Bm,
    float* __restrict__ C, int M, int N, int K)
{
    constexpr int NTW   = BN / 16;            // n-tiles (8 cols) per warp: 8 or 4
    constexpr int BCH   = (BN * 8) / 256;     // B 16B-chunks per thread: 4 or 2
    constexpr int STAGE = 16384 + BN * 128;   // A 16KB + B BN*128

    extern __shared__ char dynsmem[];
    const int tid = threadIdx.x;
    const int wid = tid >> 5, lane = tid & 31;
    const int bm = blockIdx.y * 128, bn = blockIdx.x * BN;
    const int m_warp = (wid >> 1) * 32, n_warp = (wid & 1) * (BN / 2);

    uint32_t raw = smem_u32(dynsmem);
    const uint32_t sbase = (raw + 1023u) & ~1023u;

    uint32_t pswA[4], pswB[BCH];
    const __nv_bfloat16 *Ap[4], *Bp[BCH];
#pragma unroll
    for (int i = 0; i < 4; i++) {
        const int chunk = tid + i * 256;
        const int row = chunk >> 3, c = chunk & 7;
        pswA[i] = row * 128 + ((c ^ (row & 7)) << 4);
        Ap[i] = A + (size_t)(bm + row) * K + c * 8;
    }
#pragma unroll
    for (int i = 0; i < BCH; i++) {
        const int chunk = tid + i * 256;
        const int row = chunk >> 3, c = chunk & 7;
        pswB[i] = row * 128 + ((c ^ (row & 7)) << 4);
        Bp[i] = Bm + (size_t)(bn + row) * K + c * 8;
    }

    const int khA = lane >> 4;
    const int rA0 = m_warp + (lane & 15), rA1 = rA0 + 16;
    const uint32_t offA0 = rA0 * 128, offA1 = rA1 * 128;
    const int x7A0 = rA0 & 7, x7A1 = rA1 & 7;
    const int khB = (lane >> 3) & 1;
    const int rb_off = (lane & 7) + ((lane >> 4) << 3);
    uint32_t offB[NTW / 2]; int x7B[NTW / 2];
#pragma unroll
    for (int np = 0; np < NTW / 2; np++) {
        const int r = n_warp + np * 16 + rb_off;
        offB[np] = r * 128; x7B[np] = r & 7;
    }

    float acc[2][NTW][4];
#pragma unroll
    for (int mt = 0; mt < 2; mt++)
#pragma unroll
        for (int nt = 0; nt < NTW; nt++)
#pragma unroll
            for (int e = 0; e < 4; e++) acc[mt][nt][e] = 0.f;

    const int nk = K >> 6;
    {
        const uint32_t s = sbase;
#pragma unroll
        for (int i = 0; i < 4; i++) CP_ASYNC16(s + pswA[i], Ap[i]);
#pragma unroll
        for (int i = 0; i < BCH; i++) CP_ASYNC16(s + 16384 + pswB[i], Bp[i]);
        CP_COMMIT();
    }

    for (int kc = 0; kc < nk; kc++) {
        const int buf = kc & 1;
        if (kc + 1 < nk) {
            const uint32_t s = sbase + (buf ^ 1) * STAGE;
            const int ko = (kc + 1) << 6;
#pragma unroll
            for (int i = 0; i < 4; i++) CP_ASYNC16(s + pswA[i], Ap[i] + ko);
#pragma unroll
            for (int i = 0; i < BCH; i++) CP_ASYNC16(s + 16384 + pswB[i], Bp[i] + ko);
            CP_COMMIT();
            CP_WAIT1();
        } else {
            CP_WAIT0();
        }
        __syncthreads();

        const uint32_t sA = sbase + buf * STAGE;
        const uint32_t sB = sA + 16384;
#pragma unroll
        for (int ks = 0; ks < 4; ks++) {
            uint32_t a0[4], a1[4];
            const int cA = 2 * ks + khA;
            ldsm_x4(a0, sA + offA0 + ((cA ^ x7A0) << 4));
            ldsm_x4(a1, sA + offA1 + ((cA ^ x7A1) << 4));
            uint32_t b[NTW][2];
            const int cB = 2 * ks + khB;
#pragma unroll
            for (int np = 0; np < NTW / 2; np++) {
                uint32_t r[4];
                ldsm_x4(r, sB + offB[np] + ((cB ^ x7B[np]) << 4));
                b[2 * np][0] = r[0]; b[2 * np][1] = r[1];
                b[2 * np + 1][0] = r[2]; b[2 * np + 1][1] = r[3];
            }
#pragma unroll
            for (int nt = 0; nt < NTW; nt++) {
                mma16816(acc[0][nt], a0, b[nt]);
                mma16816(acc[1][nt], a1, b[nt]);
            }
        }
        __syncthreads();
    }

    const int tr = lane >> 2, tc = (lane & 3) * 2;
#pragma unroll
    for (int mt = 0; mt < 2; mt++) {
        const int row0 = bm + m_warp + mt * 16 + tr;
#pragma unroll
        for (int nt = 0; nt < NTW; nt++) {
            const int col = bn + n_warp + nt * 8 + tc;
            *(float2*)(C + (size_t)row0 * N + col)       = make_float2(acc[mt][nt][0], acc[mt][nt][1]);
            *(float2*)(C + (size_t)(row0 + 8) * N + col) = make_float2(acc[mt][nt][2], acc[mt][nt][3]);
        }
    }
}

// ---------------- prep ----------------
__global__ __launch_bounds__(128) void prep_kernel(
    const float* __restrict__ dt_bias,
    const float* __restrict__ Bnw, const float* __restrict__ Cnw)
{
    const int bt = blockIdx.x;
    const int n  = threadIdx.x;
    const size_t base = (size_t)bt * DP;

    float Bv = g_proj[base + 2 * DI + n];
    float Cv = g_proj[base + 2 * DI + DS + n];
    float sb = Bv * Bv, sc = Cv * Cv;
#pragma unroll
    for (int o = 16; o > 0; o >>= 1) {
        sb += __shfl_xor_sync(0xffffffffu, sb, o);
        sc += __shfl_xor_sync(0xffffffffu, sc, o);
    }
    __shared__ float red[2][4];
    const int w = n >> 5, ln = n & 31;
    if (ln == 0) { red[0][w] = sb; red[1][w] = sc; }
    __syncthreads();
    float tb = red[0][0] + red[0][1] + red[0][2] + red[0][3];
    float tc = red[1][0] + red[1][1] + red[1][2] + red[1][3];

    g_Bn[bt * DS + n] = Bv * rsqrtf(tb * (1.f / DS) + 1e-5f) * Bnw[n];
    g_Cn[bt * DS + n] = Cv * rsqrtf(tc * (1.f / DS) + 1e-5f) * Cnw[n];

    if (n < NH) {
        float dd = g_proj[base + 2 * DI + 2 * DS + n];
        float dA = g_proj[base + 2 * DI + 2 * DS + NH + n];
        float tr = g_proj[base + 2 * DI + 2 * DS + 2 * NH + n];
        float dt = softplusf(dd + dt_bias[n]);
        float a  = -softplusf(dA);
        a = fminf(a, -1e-4f);
        g_dt [bt * NH + n] = dt;
        g_gd [bt * NH + n] = expf(a * dt);
        g_lam[bt * NH + n] = 1.f / (1.f + expf(-tr));
    }
}

// ---------------- theta: parallel 3-pass ----------------
__global__ __launch_bounds__(1024) void thetaA_kernel()
{
    const int c = blockIdx.x, b = blockIdx.y;
    __shared__ float sdt[1024], sang[1024];
    const int i = threadIdx.x;
    const int bt0 = b * L_ + c * 32;
    sdt[i] = g_dt[bt0 * NH + i];
    const int s = i >> 5, j = i & 31;
    sang[i] = g_proj[(size_t)(bt0 + s) * DP + (DP - NA) + j];
    __syncthreads();
    const int h = i >> 5;
    float acc = 0.f;
#pragma unroll
    for (int ss = 0; ss < 32; ss++)
        acc = fmaf(sdt[ss * 32 + h], sang[ss * 32 + j], acc);
    g_csum[(b * 32 + c) * 1024 + i] = acc;
}

__global__ __launch_bounds__(1024) void thetaB_kernel()
{
    const int b = blockIdx.x, i = threadIdx.x;
    float run = 0.f;
    for (int c = 0; c < 32; c++) {
        float v = g_csum[(b * 32 + c) * 1024 + i];
        g_cpre[(b * 32 + c) * 1024 + i] = run;
        run += v;
    }
}

__global__ __launch_bounds__(1024) void thetaC_kernel()
{
    const int c = blockIdx.x, b = blockIdx.y;
    __shared__ float sdt[1024], sang[1024];
    const int i = threadIdx.x;
    const int bt0 = b * L_ + c * 32;
    sdt[i] = g_dt[bt0 * NH + i];
    const int s0 = i >> 5, j = i & 31;
    sang[i] = g_proj[(size_t)(bt0 + s0) * DP + (DP - NA) + j];
    __syncthreads();
    const int h = i >> 5;
    float run = g_cpre[(b * 32 + c) * 1024 + i];
#pragma unroll
    for (int s = 0; s < 32; s++) {
        run = fmaf(sdt[s * 32 + h], sang[s * 32 + j], run);
        float sn, cs;
        __sincosf(run, &sn, &cs);
        const int o = (bt0 + s) * 1024 + i;
        g_cos[o] = cs;
        g_sin[o] = sn;
    }
}

// ---------------- tiled sequential SSM scan (exact R8 configuration) ----------------
#define ST 16
#define NTILE (L_ / ST)

struct __align__(16) ScanSmem {
    float sB[2][ST][128];
    float sC[2][ST][128];
    float sCs[2][ST][32];
    float sSn[2][ST][32];
    float sX[2][ST][32];
    float sScal[2][3][ST];
    float sYp[ST][32][8];
};
#define SCAN_SMEM_BYTES ((int)sizeof(ScanSmem))

__global__ __launch_bounds__(256) void scan_kernel(
    const float* __restrict__ Bbias, const float* __restrict__ Cbias)
{
    extern __shared__ char dynsmem[];
    ScanSmem* s = (ScanSmem*)dynsmem;

    const int phalf = blockIdx.x;
    const int h = blockIdx.y;
    const int b = blockIdx.z;
    const int tid = threadIdx.x;
    const int pp = tid >> 4;
    const int ng = tid & 15;
    const int n0 = ng * 8;
    const int pstart = phalf * 32;

    const int nn = tid & 63;
    const int tq = (tid >> 6) & 1;
    const float* biasPtr = (tid < 128) ? Bbias : Cbias;
    float ba1, ba2;
    if (nn < 32) { ba1 = biasPtr[h * DS + nn];      ba2 = biasPtr[h * DS + nn + 32]; }
    else         { ba1 = biasPtr[h * DS + nn + 32]; ba2 = biasPtr[h * DS + nn + 64]; }

#define PREFETCH(k, pbuf) do {                                                   \
        const int bt0_ = b * L_ + (k) * ST;                                      \
        _Pragma("unroll")                                                        \
        for (int r = 0; r < 2; r++) {                                            \
            const int q = tid + r * 256, tp = q >> 5, seg = q & 31;              \
            CP_ASYNC16(smem_u32(&s->sB[pbuf][tp][seg * 4]),                      \
                       &g_Bn[(bt0_ + tp) * DS + seg * 4]);                       \
            CP_ASYNC16(smem_u32(&s->sC[pbuf][tp][seg * 4]),                      \
                       &g_Cn[(bt0_ + tp) * DS + seg * 4]);                       \
        }                                                                        \
        if (tid < 128) {                                                         \
            const int tp = tid >> 3, seg = tid & 7;                              \
            CP_ASYNC16(smem_u32(&s->sCs[pbuf][tp][seg * 4]),                     \
                       &g_cos[((bt0_ + tp) * NH + h) * NA + seg * 4]);           \
            CP_ASYNC16(smem_u32(&s->sSn[pbuf][tp][seg * 4]),                     \
                       &g_sin[((bt0_ + tp) * NH + h) * NA + seg * 4]);           \
            CP_ASYNC16(smem_u32(&s->sX[pbuf][tp][seg * 4]),                      \
                       &g_proj[(size_t)(bt0_ + tp) * DP + DI + h * HD + pstart + seg * 4]); \
        }                                                                        \
        if (tid < 48) {                                                          \
            const int which = tid >> 4, tp = tid & 15;                           \
            const float* srcs = (which == 0) ? g_dt : (which == 1) ? g_gd : g_lam; \
            CP_ASYNC4(smem_u32(&s->sScal[pbuf][which][tp]),                      \
                      &srcs[(bt0_ + tp) * NH + h]);                              \
        }                                                                        \
        CP_COMMIT();                                                             \
    } while (0)

    ull h0[4], h1[4], Bp[4];
#pragma unroll
    for (int i = 0; i < 4; i++) { h0[i] = 0ull; h1[i] = 0ull; Bp[i] = 0ull; }
    float xp0 = 0.f, xp1 = 0.f;

    PREFETCH(0, 0);

    for (int k = 0; k < NTILE; k++) {
        const int buf = k & 1;
        if (k + 1 < NTILE) {
            PREFETCH(k + 1, buf ^ 1);
            CP_WAIT1();
        } else {
            CP_WAIT0();
        }
        __syncthreads();

        // ---- bias + RoPE stage ----
        {
            float* mat = (tid < 128) ? &s->sB[buf][0][0] : &s->sC[buf][0][0];
#pragma unroll
            for (int tp = tq; tp < ST; tp += 2) {
                float* rb = mat + tp * 128;
                if (nn < 32) {
                    const float cv = s->sCs[buf][tp][nn], sv = s->sSn[buf][tp][nn];
                    const float v1 = rb[nn] + ba1, v2 = rb[nn + 32] + ba2;
                    rb[nn]      = v1 * cv - v2 * sv;
                    rb[nn + 32] = v1 * sv + v2 * cv;
                } else {
                    rb[nn + 32] += ba1;
                    rb[nn + 64] += ba2;
                }
            }
        }
        __syncthreads();

        // ---- 16 timesteps: state update, partial-y to smem ----
#pragma unroll
        for (int tp = 0; tp < ST; tp++) {
            const float dt  = s->sScal[buf][0][tp];
            const float g   = s->sScal[buf][1][tp];
            const float lam = s->sScal[buf][2][tp];
            const float xc0 = s->sX[buf][tp][pp];
            const float xc1 = s->sX[buf][tp][pp + 16];
            const float k1 = dt * lam;
            const float k2 = dt * (1.f - lam) * g;
            const ull g2  = pk2(g);
            const ull c1a = pk2(k1 * xc0);
            const ull c2a = pk2(k2 * xp0);
            const ull c1b = pk2(k1 * xc1);
            const ull c2b = pk2(k2 * xp1);

            const ulonglong2 b01 = *(const ulonglong2*)&s->sB[buf][tp][n0];
            const ulonglong2 b23 = *(const ulonglong2*)&s->sB[buf][tp][n0 + 4];
            const ulonglong2 c01 = *(const ulonglong2*)&s->sC[buf][tp][n0];
            const ulonglong2 c23 = *(const ulonglong2*)&s->sC[buf][tp][n0 + 4];
            const ull bv[4] = { b01.x, b01.y, b23.x, b23.y };
            const ull cv[4] = { c01.x, c01.y, c23.x, c23.y };

            ull y0 = 0ull, y1 = 0ull;
#pragma unroll
            for (int j = 0; j < 4; j++) {
                ull t0 = mul2(c2a, Bp[j]);
                t0 = fma2(c1a, bv[j], t0);
                h0[j] = fma2(g2, h0[j], t0);
                y0 = fma2(h0[j], cv[j], y0);
                ull t1 = mul2(c2b, Bp[j]);
                t1 = fma2(c1b, bv[j], t1);
                h1[j] = fma2(g2, h1[j], t1);
                y1 = fma2(h1[j], cv[j], y1);
                Bp[j] = bv[j];
            }
            xp0 = xc0; xp1 = xc1;

            float y0f = sum2(y0), y1f = sum2(y1);
            y0f += __shfl_xor_sync(0xffffffffu, y0f, 8);
            y1f += __shfl_xor_sync(0xffffffffu, y1f, 8);
            if ((ng & 8) == 0) {
                s->sYp[tp][pp][ng]      = y0f;
                s->sYp[tp][pp + 16][ng] = y1f;
            }
        }
        __syncthreads();

        // ---- batched per-tile reduce ----
        {
            const int t  = tid >> 4;
            const int p0 = (tid & 15) * 2;
            float4 a0 = *(const float4*)&s->sYp[t][p0][0];
            float4 a1 = *(const float4*)&s->sYp[t][p0][4];
            float4 b0 = *(const float4*)&s->sYp[t][p0 + 1][0];
            float4 b1 = *(const float4*)&s->sYp[t][p0 + 1][4];
            float v0 = (a0.x + a0.y) + (a0.z + a0.w) + (a1.x + a1.y) + (a1.z + a1.w);
            float v1 = (b0.x + b0.y) + (b0.z + b0.w) + (b1.x + b1.y) + (b1.z + b1.w);
            *(float2*)&g_y[(size_t)(b * L_ + k * ST + t) * DI + h * HD + pstart + p0] =
                make_float2(v0, v1);
        }
        __syncthreads();
    }
#undef PREFETCH
}

// ---------------- epilogue ----------------
__global__ __launch_bounds__(256) void epi_kernel(const float* __restrict__ Dp)
{
    const int idx = blockIdx.x * 256 + threadIdx.x;
    const int bt = idx >> 11;
    const int c  = idx & 2047;
    const int h  = c >> 6;
    float y = g_y[idx];
    float x = g_proj[(size_t)bt * DP + DI + c];
    float z = g_proj[(size_t)bt * DP + c];
    float sil = z / (1.f + expf(-z));
    float v = (y + Dp[h] * x) * sil;
    __nv_bfloat16 hh = __float2bfloat16(v);
    __nv_bfloat16 ll = __float2bfloat16(v - __bfloat162float(hh));
    const size_t rb = (size_t)bt * K2X;
    g_y2[rb + c]          = hh;
    g_y2[rb + DI + c]     = ll;
    g_y2[rb + 2 * DI + c] = hh;
}

// ---------------- launch ----------------
extern "C" void kernel_launch(void* const* d_in, const int* in_sizes, int n_in,
                              void* d_out, int out_size)
{
    (void)in_sizes; (void)n_in; (void)out_size;
    const float* u        = (const float*)d_in[0];
    const float* W_in     = (const float*)d_in[1];
    const float* W_out    = (const float*)d_in[2];
    const float* dt_bias  = (const float*)d_in[3];
    const float* B_bias   = (const float*)d_in[4];
    const float* C_bias   = (const float*)d_in[5];
    const float* B_norm_w = (const float*)d_in[6];
    const float* C_norm_w = (const float*)d_in[7];
    const float* D_param  = (const float*)d_in[8];
    float* out = (float*)d_out;

    void *p_proj, *p_u2, *p_wi2, *p_y2, *p_wo2;
    cudaGetSymbolAddress(&p_proj, g_proj);
    cudaGetSymbolAddress(&p_u2,  g_u2);
    cudaGetSymbolAddress(&p_wi2, g_Wi2);
    cudaGetSymbolAddress(&p_y2,  g_y2);
    cudaGetSymbolAddress(&p_wo2, g_Wo2);

    const int GS1 = 2 * (16384 + 128 * 128) + 1024;   // BN=128 stage pair
    const int GS2 = 2 * (16384 + 64 * 128) + 1024;    // BN=64  stage pair
    cudaFuncSetAttribute(gemm_bf16<128>, cudaFuncAttributeMaxDynamicSharedMemorySize, GS1);
    cudaFuncSetAttribute(gemm_bf16<64>,  cudaFuncAttributeMaxDynamicSharedMemorySize, GS2);
    cudaFuncSetAttribute(scan_kernel, cudaFuncAttributeMaxDynamicSharedMemorySize, SCAN_SMEM_BYTES);

    // 0) folded bf16 splits
    split_A<<<(BT * DM / 4 + 255) / 256, 256>>>(u,     (__nv_bfloat16*)p_u2,  DM / 4, BT * DM / 4);
    split_B<<<(DP * DM / 4 + 255) / 256, 256>>>(W_in,  (__nv_bfloat16*)p_wi2, DM / 4, DP * DM / 4);
    split_B<<<(DM * DI / 4 + 255) / 256, 256>>>(W_out, (__nv_bfloat16*)p_wo2, DI / 4, DM * DI / 4);

    // 1) proj = u @ W_in^T  (BN=128, proven config)
    gemm_bf16<128><<<dim3(DP / 128, BT / 128), 256, GS1>>>(
        (const __nv_bfloat16*)p_u2, (const __nv_bfloat16*)p_wi2,
        (float*)p_proj, BT, DP, K1X);

    // 2) rmsnorm + head scalars
    prep_kernel<<<BT, 128>>>(dt_bias, B_norm_w, C_norm_w);

    // 3) theta: parallel chunked cumsum + sincos
    thetaA_kernel<<<dim3(32, B_), 1024>>>();
    thetaB_kernel<<<B_, 1024>>>();
    thetaC_kernel<<<dim3(32, B_), 1024>>>();

    // 4) tiled sequential scan (exact R8)
    scan_kernel<<<dim3(2, NH, B_), 256, SCAN_SMEM_BYTES>>>(B_bias, C_bias);

    // 5) gated epilogue
    epi_kernel<<<(BT * DI) / 256, 256>>>(D_param);

    // 6) out = yact @ W_out^T  (BN=64 -> 256 CTAs, better chip coverage)
    gemm_bf16<64><<<dim3(DM / 64, BT / 128), 256, GS2>>>(
        (const __nv_bfloat16*)p_y2, (const __nv_bfloat16*)p_wo2,
        out, BT, DM, K2X);
}

// round 17
// speedup vs baseline: 1.4692x; 1.0303x over previous
#include <cuda_runtime.h>
#include <cuda_bf16.h>
#include <math.h>
#include <stdint.h>

#define B_  2
#define L_  1024
#define DM  1024
#define DI  2048
#define NH  32
#define HD  64
#define DS  128
#define NA  32
#define DP  4480   // 2*DI + 2*DS + 3*NH + NA
#define BT  (B_*L_)

#define K1X (3*DM)      // gemm1 folded K' = 3072
#define K2X (3*DI)      // gemm2 folded K' = 6144

// ---------------- device scratch ----------------
__device__ float g_proj[(size_t)BT * DP];
__device__ float g_Bn  [BT * DS];
__device__ float g_Cn  [BT * DS];
__device__ float g_dt  [BT * NH];
__device__ float g_gd  [BT * NH];
__device__ float g_lam [BT * NH];
__device__ float g_cos [BT * NH * NA];
__device__ float g_sin [BT * NH * NA];

__device__ __nv_bfloat16 g_u2 [(size_t)BT * K1X];
__device__ __nv_bfloat16 g_Wi2[(size_t)DP * K1X];
__device__ __nv_bfloat16 g_y2 [(size_t)BT * K2X];
__device__ __nv_bfloat16 g_Wo2[(size_t)DM * K2X];

typedef unsigned long long ull;

__device__ __forceinline__ float softplusf(float x) {
    return (x > 20.f) ? x : log1pf(expf(x));
}
__device__ __forceinline__ uint32_t smem_u32(const void* p) {
    uint32_t a;
    asm("{ .reg .u64 t; cvta.to.shared.u64 t, %1; cvt.u32.u64 %0, t; }" : "=r"(a) : "l"(p));
    return a;
}

// ---- packed f32x2 helpers ----
__device__ __forceinline__ ull pk2(float v) {
    ull r; asm("mov.b64 %0, {%1, %1};" : "=l"(r) : "f"(v)); return r;
}
__device__ __forceinline__ ull fma2(ull a, ull b, ull c) {
    ull d; asm("fma.rn.f32x2 %0, %1, %2, %3;" : "=l"(d) : "l"(a), "l"(b), "l"(c)); return d;
}
__device__ __forceinline__ ull mul2(ull a, ull b) {
    ull d; asm("mul.rn.f32x2 %0, %1, %2;" : "=l"(d) : "l"(a), "l"(b)); return d;
}
__device__ __forceinline__ float sum2(ull a) {
    float x, y;
    asm("mov.b64 {%0, %1}, %2;" : "=f"(x), "=f"(y) : "l"(a));
    return x + y;
}

#define CP_ASYNC16(dst, src) \
    asm volatile("cp.async.cg.shared.global [%0], [%1], 16;" :: "r"(dst), "l"(src))
#define CP_ASYNC4(dst, src) \
    asm volatile("cp.async.ca.shared.global [%0], [%1], 4;" :: "r"(dst), "l"(src))
#define CP_COMMIT() asm volatile("cp.async.commit_group;")
#define CP_WAIT1()  asm volatile("cp.async.wait_group 1;")
#define CP_WAIT0()  asm volatile("cp.async.wait_group 0;")

__device__ __forceinline__ void ldsm_x4(uint32_t* r, uint32_t addr) {
    asm volatile("ldmatrix.sync.aligned.m8n8.x4.shared.b16 {%0,%1,%2,%3}, [%4];"
        : "=r"(r[0]), "=r"(r[1]), "=r"(r[2]), "=r"(r[3]) : "r"(addr));
}
__device__ __forceinline__ void mma16816(float* d, const uint32_t* a, const uint32_t* b) {
    asm volatile(
        "mma.sync.aligned.m16n8k16.row.col.f32.bf16.bf16.f32 "
        "{%0,%1,%2,%3},{%4,%5,%6,%7},{%8,%9},{%0,%1,%2,%3};"
        : "+f"(d[0]), "+f"(d[1]), "+f"(d[2]), "+f"(d[3])
        : "r"(a[0]), "r"(a[1]), "r"(a[2]), "r"(a[3]), "r"(b[0]), "r"(b[1]));
}

// ---------------- split kernels ----------------
__global__ __launch_bounds__(256) void split_A(
    const float* __restrict__ src, __nv_bfloat16* __restrict__ dst, int Kq, int n4)
{
    int i = blockIdx.x * 256 + threadIdx.x;
    if (i >= n4) return;
    int row = i / Kq, k4 = (i - row * Kq) * 4;
    float4 v = *(const float4*)(src + (size_t)row * (Kq * 4) + k4);
    __nv_bfloat162 h01 = __floats2bfloat162_rn(v.x, v.y);
    __nv_bfloat162 h23 = __floats2bfloat162_rn(v.z, v.w);
    __nv_bfloat162 l01 = __floats2bfloat162_rn(v.x - __low2float(h01), v.y - __high2float(h01));
    __nv_bfloat162 l23 = __floats2bfloat162_rn(v.z - __low2float(h23), v.w - __high2float(h23));
    const int K = Kq * 4;
    __nv_bfloat162* d0 = (__nv_bfloat162*)(dst + (size_t)row * 3 * K + k4);
    __nv_bfloat162* d1 = (__nv_bfloat162*)(dst + (size_t)row * 3 * K + K + k4);
    __nv_bfloat162* d2 = (__nv_bfloat162*)(dst + (size_t)row * 3 * K + 2 * K + k4);
    d0[0] = h01; d0[1] = h23;
    d1[0] = l01; d1[1] = l23;
    d2[0] = h01; d2[1] = h23;
}
__global__ __launch_bounds__(256) void split_B(
    const float* __restrict__ src, __nv_bfloat16* __restrict__ dst, int Kq, int n4)
{
    int i = blockIdx.x * 256 + threadIdx.x;
    if (i >= n4) return;
    int row = i / Kq, k4 = (i - row * Kq) * 4;
    float4 v = *(const float4*)(src + (size_t)row * (Kq * 4) + k4);
    __nv_bfloat162 h01 = __floats2bfloat162_rn(v.x, v.y);
    __nv_bfloat162 h23 = __floats2bfloat162_rn(v.z, v.w);
    __nv_bfloat162 l01 = __floats2bfloat162_rn(v.x - __low2float(h01), v.y - __high2float(h01));
    __nv_bfloat162 l23 = __floats2bfloat162_rn(v.z - __low2float(h23), v.w - __high2float(h23));
    const int K = Kq * 4;
    __nv_bfloat162* d0 = (__nv_bfloat162*)(dst + (size_t)row * 3 * K + k4);
    __nv_bfloat162* d1 = (__nv_bfloat162*)(dst + (size_t)row * 3 * K + K + k4);
    __nv_bfloat162* d2 = (__nv_bfloat162*)(dst + (size_t)row * 3 * K + 2 * K + k4);
    d0[0] = h01; d0[1] = h23;
    d1[0] = h01; d1[1] = h23;
    d2[0] = l01; d2[1] = l23;
}

// ---------------- bf16 mma.sync GEMM (R8 2-stage, proven) ----------------
#define GS_STAGE 32768
#define GS_TOTAL (2 * GS_STAGE + 1024)

__global__ __launch_bounds__(256) void gemm_bf16(
    const __nv_bfloat16* __restrict__ A, const __nv_bfloat16* __restrict__ Bm,
    float* __restrict__ C, int M, int N, int K)
{
    extern __shared__ char dynsmem[];
    const int tid = threadIdx.x;
    const int wid = tid >> 5, lane = tid & 31;
    const int bm = blockIdx.y * 128, bn = blockIdx.x * 128;
    const int m_warp = (wid >> 1) * 32, n_warp = (wid & 1) * 64;

    uint32_t raw = smem_u32(dynsmem);
    const uint32_t sbase = (raw + 1023u) & ~1023u;

    uint32_t psw[4];
    const __nv_bfloat16 *Ap[4], *Bp[4];
#pragma unroll
    for (int i = 0; i < 4; i++) {
        const int chunk = tid + i * 256;
        const int row = chunk >> 3, c = chunk & 7;
        psw[i] = row * 128 + ((c ^ (row & 7)) << 4);
        Ap[i] = A  + (size_t)(bm + row) * K + c * 8;
        Bp[i] = Bm + (size_t)(bn + row) * K + c * 8;
    }

    const int khA = lane >> 4;
    const int rA0 = m_warp + (lane & 15), rA1 = rA0 + 16;
    const uint32_t offA0 = rA0 * 128, offA1 = rA1 * 128;
    const int x7A0 = rA0 & 7, x7A1 = rA1 & 7;
    const int khB = (lane >> 3) & 1;
    const int rb_off = (lane & 7) + ((lane >> 4) << 3);
    uint32_t offB[4]; int x7B[4];
#pragma unroll
    for (int np = 0; np < 4; np++) {
        const int r = n_warp + np * 16 + rb_off;
        offB[np] = r * 128; x7B[np] = r & 7;
    }

    float acc[2][8][4];
#pragma unroll
    for (int mt = 0; mt < 2; mt++)
#pragma unroll
        for (int nt = 0; nt < 8; nt++)
#pragma unroll
            for (int e = 0; e < 4; e++) acc[mt][nt][e] = 0.f;

    const int nk = K >> 6;
    {
        const uint32_t s = sbase;
#pragma unroll
        for (int i = 0; i < 4; i++) {
            CP_ASYNC16(s + psw[i], Ap[i]);
            CP_ASYNC16(s + 16384 + psw[i], Bp[i]);
        }
        CP_COMMIT();
    }

    for (int kc = 0; kc < nk; kc++) {
        const int buf = kc & 1;
        if (kc + 1 < nk) {
            const uint32_t s = sbase + (buf ^ 1) * GS_STAGE;
            const int ko = (kc + 1) << 6;
#pragma unroll
            for (int i = 0; i < 4; i++) {
                CP_ASYNC16(s + psw[i], Ap[i] + ko);
                CP_ASYNC16(s + 16384 + psw[i], Bp[i] + ko);
            }
            CP_COMMIT();
            CP_WAIT1();
        } else {
            CP_WAIT0();
        }
        __syncthreads();

        const uint32_t sA = sbase + buf * GS_STAGE;
        const uint32_t sB = sA + 16384;
#pragma unroll
        for (int ks = 0; ks < 4; ks++) {
            uint32_t a0[4], a1[4];
            const int cA = 2 * ks + khA;
            ldsm_x4(a0, sA + offA0 + ((cA ^ x7A0) << 4));
            ldsm_x4(a1, sA + offA1 + ((cA ^ x7A1) << 4));
            uint32_t b[8][2];
            const int cB = 2 * ks + khB;
#pragma unroll
            for (int np = 0; np < 4; np++) {
                uint32_t r[4];
                ldsm_x4(r, sB + offB[np] + ((cB ^ x7B[np]) << 4));
                b[2 * np][0] = r[0]; b[2 * np][1] = r[1];
                b[2 * np + 1][0] = r[2]; b[2 * np + 1][1] = r[3];
            }
#pragma unroll
            for (int nt = 0; nt < 8; nt++) {
                mma16816(acc[0][nt], a0, b[nt]);
                mma16816(acc[1][nt], a1, b[nt]);
            }
        }
        __syncthreads();
    }

    const int tr = lane >> 2, tc = (lane & 3) * 2;
#pragma unroll
    for (int mt = 0; mt < 2; mt++) {
        const int row0 = bm + m_warp + mt * 16 + tr;
#pragma unroll
        for (int nt = 0; nt < 8; nt++) {
            const int col = bn + n_warp + nt * 8 + tc;
            *(float2*)(C + (size_t)row0 * N + col)       = make_float2(acc[mt][nt][0], acc[mt][nt][1]);
            *(float2*)(C + (size_t)(row0 + 8) * N + col) = make_float2(acc[mt][nt][2], acc[mt][nt][3]);
        }
    }
}

// ---------------- prep ----------------
__global__ __launch_bounds__(128) void prep_kernel(
    const float* __restrict__ dt_bias,
    const float* __restrict__ Bnw, const float* __restrict__ Cnw)
{
    const int bt = blockIdx.x;
    const int n  = threadIdx.x;
    const size_t base = (size_t)bt * DP;

    float Bv = g_proj[base + 2 * DI + n];
    float Cv = g_proj[base + 2 * DI + DS + n];
    float sb = Bv * Bv, sc = Cv * Cv;
#pragma unroll
    for (int o = 16; o > 0; o >>= 1) {
        sb += __shfl_xor_sync(0xffffffffu, sb, o);
        sc += __shfl_xor_sync(0xffffffffu, sc, o);
    }
    __shared__ float red[2][4];
    const int w = n >> 5, ln = n & 31;
    if (ln == 0) { red[0][w] = sb; red[1][w] = sc; }
    __syncthreads();
    float tb = red[0][0] + red[0][1] + red[0][2] + red[0][3];
    float tc = red[1][0] + red[1][1] + red[1][2] + red[1][3];

    g_Bn[bt * DS + n] = Bv * rsqrtf(tb * (1.f / DS) + 1e-5f) * Bnw[n];
    g_Cn[bt * DS + n] = Cv * rsqrtf(tc * (1.f / DS) + 1e-5f) * Cnw[n];

    if (n < NH) {
        float dd = g_proj[base + 2 * DI + 2 * DS + n];
        float dA = g_proj[base + 2 * DI + 2 * DS + NH + n];
        float tr = g_proj[base + 2 * DI + 2 * DS + 2 * NH + n];
        float dt = softplusf(dd + dt_bias[n]);
        float a  = -softplusf(dA);
        a = fminf(a, -1e-4f);
        g_dt [bt * NH + n] = dt;
        g_gd [bt * NH + n] = expf(a * dt);
        g_lam[bt * NH + n] = 1.f / (1.f + expf(-tr));
    }
}

// ---------------- theta: single kernel (per-(b,h) block, chunk prefix in smem) ----------------
__global__ __launch_bounds__(1024) void theta_kernel()
{
    const int h = blockIdx.x;
    const int b = blockIdx.y;
    const int i = threadIdx.x;

    __shared__ float sdt[1024];
    __shared__ float ssum[32][33];

    sdt[i] = g_dt[(b * L_ + i) * NH + h];
    __syncthreads();

    const int c = i >> 5, j = i & 31;
    const size_t abase = (size_t)(b * L_ + c * 32) * DP + (DP - NA) + j;

    float acc = 0.f;
#pragma unroll
    for (int s2 = 0; s2 < 32; s2++)
        acc = fmaf(sdt[c * 32 + s2], g_proj[abase + (size_t)s2 * DP], acc);
    ssum[c][j] = acc;
    __syncthreads();

    float run = 0.f;
    for (int cc = 0; cc < c; cc++)
        run += ssum[cc][j];

#pragma unroll
    for (int s2 = 0; s2 < 32; s2++) {
        run = fmaf(sdt[c * 32 + s2], g_proj[abase + (size_t)s2 * DP], run);
        float sn, cs;
        __sincosf(run, &sn, &cs);
        const int o = ((b * L_ + c * 32 + s2) * NH + h) * NA + j;
        g_cos[o] = cs;
        g_sin[o] = sn;
    }
}

// ---------------- tiled sequential SSM scan (R8 core + fused gated epilogue) ----------------
#define ST 16
#define NTILE (L_ / ST)

struct __align__(16) ScanSmem {
    float sB[2][ST][128];
    float sC[2][ST][128];
    float sCs[2][ST][32];
    float sSn[2][ST][32];
    float sX[2][ST][32];
    float sZ[2][ST][32];
    float sScal[2][3][ST];
    float sYp[ST][32][8];
};
#define SCAN_SMEM_BYTES ((int)sizeof(ScanSmem))

__global__ __launch_bounds__(256) void scan_kernel(
    const float* __restrict__ Bbias, const float* __restrict__ Cbias,
    const float* __restrict__ Dp)
{
    extern __shared__ char dynsmem[];
    ScanSmem* s = (ScanSmem*)dynsmem;

    const int phalf = blockIdx.x;
    const int h = blockIdx.y;
    const int b = blockIdx.z;
    const int tid = threadIdx.x;
    const int pp = tid >> 4;
    const int ng = tid & 15;
    const int n0 = ng * 8;
    const int pstart = phalf * 32;

    const int nn = tid & 63;
    const int tq = (tid >> 6) & 1;
    const float* biasPtr = (tid < 128) ? Bbias : Cbias;
    float ba1, ba2;
    if (nn < 32) { ba1 = biasPtr[h * DS + nn];      ba2 = biasPtr[h * DS + nn + 32]; }
    else         { ba1 = biasPtr[h * DS + nn + 32]; ba2 = biasPtr[h * DS + nn + 64]; }
    const float Dh = Dp[h];

#define PREFETCH(k, pbuf) do {                                                   \
        const int bt0_ = b * L_ + (k) * ST;                                      \
        _Pragma("unroll")                                                        \
        for (int r = 0; r < 2; r++) {                                            \
            const int q = tid + r * 256, tp = q >> 5, seg = q & 31;              \
            CP_ASYNC16(smem_u32(&s->sB[pbuf][tp][seg * 4]),                      \
                       &g_Bn[(bt0_ + tp) * DS + seg * 4]);                       \
            CP_ASYNC16(smem_u32(&s->sC[pbuf][tp][seg * 4]),                      \
                       &g_Cn[(bt0_ + tp) * DS + seg * 4]);                       \
        }                                                                        \
        if (tid < 128) {                                                         \
            const int tp = tid >> 3, seg = tid & 7;                              \
            CP_ASYNC16(smem_u32(&s->sCs[pbuf][tp][seg * 4]),                     \
                       &g_cos[((bt0_ + tp) * NH + h) * NA + seg * 4]);           \
            CP_ASYNC16(smem_u32(&s->sSn[pbuf][tp][seg * 4]),                     \
                       &g_sin[((bt0_ + tp) * NH + h) * NA + seg * 4]);           \
            CP_ASYNC16(smem_u32(&s->sX[pbuf][tp][seg * 4]),                      \
                       &g_proj[(size_t)(bt0_ + tp) * DP + DI + h * HD + pstart + seg * 4]); \
            CP_ASYNC16(smem_u32(&s->sZ[pbuf][tp][seg * 4]),                      \
                       &g_proj[(size_t)(bt0_ + tp) * DP + h * HD + pstart + seg * 4]); \
        }                                                                        \
        if (tid < 48) {                                                          \
            const int which = tid >> 4, tp = tid & 15;                           \
            const float* srcs = (which == 0) ? g_dt : (which == 1) ? g_gd : g_lam; \
            CP_ASYNC4(smem_u32(&s->sScal[pbuf][which][tp]),                      \
                      &srcs[(bt0_ + tp) * NH + h]);                              \
        }                                                                        \
        CP_COMMIT();                                                             \
    } while (0)

    ull h0[4], h1[4], Bp[4];
#pragma unroll
    for (int i = 0; i < 4; i++) { h0[i] = 0ull; h1[i] = 0ull; Bp[i] = 0ull; }
    float xp0 = 0.f, xp1 = 0.f;

    PREFETCH(0, 0);

    for (int k = 0; k < NTILE; k++) {
        const int buf = k & 1;
        if (k + 1 < NTILE) {
            PREFETCH(k + 1, buf ^ 1);
            CP_WAIT1();
        } else {
            CP_WAIT0();
        }
        __syncthreads();

        // ---- bias + RoPE stage ----
        {
            float* mat = (tid < 128) ? &s->sB[buf][0][0] : &s->sC[buf][0][0];
#pragma unroll
            for (int tp = tq; tp < ST; tp += 2) {
                float* rb = mat + tp * 128;
                if (nn < 32) {
                    const float cv = s->sCs[buf][tp][nn], sv = s->sSn[buf][tp][nn];
                    const float v1 = rb[nn] + ba1, v2 = rb[nn + 32] + ba2;
                    rb[nn]      = v1 * cv - v2 * sv;
                    rb[nn + 32] = v1 * sv + v2 * cv;
                } else {
                    rb[nn + 32] += ba1;
                    rb[nn + 64] += ba2;
                }
            }
        }
        __syncthreads();

        // ---- 16 timesteps: state update, partial-y to smem ----
#pragma unroll
        for (int tp = 0; tp < ST; tp++) {
            const float dt  = s->sScal[buf][0][tp];
            const float g   = s->sScal[buf][1][tp];
            const float lam = s->sScal[buf][2][tp];
            const float xc0 = s->sX[buf][tp][pp];
            const float xc1 = s->sX[buf][tp][pp + 16];
            const float k1 = dt * lam;
            const float k2 = dt * (1.f - lam) * g;
            const ull g2  = pk2(g);
            const ull c1a = pk2(k1 * xc0);
            const ull c2a = pk2(k2 * xp0);
            const ull c1b = pk2(k1 * xc1);
            const ull c2b = pk2(k2 * xp1);

            const ulonglong2 b01 = *(const ulonglong2*)&s->sB[buf][tp][n0];
            const ulonglong2 b23 = *(const ulonglong2*)&s->sB[buf][tp][n0 + 4];
            const ulonglong2 c01 = *(const ulonglong2*)&s->sC[buf][tp][n0];
            const ulonglong2 c23 = *(const ulonglong2*)&s->sC[buf][tp][n0 + 4];
            const ull bv[4] = { b01.x, b01.y, b23.x, b23.y };
            const ull cv[4] = { c01.x, c01.y, c23.x, c23.y };

            ull y0 = 0ull, y1 = 0ull;
#pragma unroll
            for (int j = 0; j < 4; j++) {
                ull t0 = mul2(c2a, Bp[j]);
                t0 = fma2(c1a, bv[j], t0);
                h0[j] = fma2(g2, h0[j], t0);
                y0 = fma2(h0[j], cv[j], y0);
                ull t1 = mul2(c2b, Bp[j]);
                t1 = fma2(c1b, bv[j], t1);
                h1[j] = fma2(g2, h1[j], t1);
                y1 = fma2(h1[j], cv[j], y1);
                Bp[j] = bv[j];
            }
            xp0 = xc0; xp1 = xc1;

            float y0f = sum2(y0), y1f = sum2(y1);
            y0f += __shfl_xor_sync(0xffffffffu, y0f, 8);
            y1f += __shfl_xor_sync(0xffffffffu, y1f, 8);
            if ((ng & 8) == 0) {
                s->sYp[tp][pp][ng]      = y0f;
                s->sYp[tp][pp + 16][ng] = y1f;
            }
        }
        __syncthreads();

        // ---- batched per-tile reduce + fused gated epilogue -> g_y2 (bf16 folded) ----
        {
            const int t  = tid >> 4;
            const int p0 = (tid & 15) * 2;
            float4 a0 = *(const float4*)&s->sYp[t][p0][0];
            float4 a1 = *(const float4*)&s->sYp[t][p0][4];
            float4 b0 = *(const float4*)&s->sYp[t][p0 + 1][0];
            float4 b1 = *(const float4*)&s->sYp[t][p0 + 1][4];
            float v0 = (a0.x + a0.y) + (a0.z + a0.w) + (a1.x + a1.y) + (a1.z + a1.w);
            float v1 = (b0.x + b0.y) + (b0.z + b0.w) + (b1.x + b1.y) + (b1.z + b1.w);

            const float x0 = s->sX[buf][t][p0], x1 = s->sX[buf][t][p0 + 1];
            const float z0 = s->sZ[buf][t][p0], z1 = s->sZ[buf][t][p0 + 1];
            const float w0 = (v0 + Dh * x0) * (z0 / (1.f + expf(-z0)));
            const float w1 = (v1 + Dh * x1) * (z1 / (1.f + expf(-z1)));

            __nv_bfloat162 hh = __floats2bfloat162_rn(w0, w1);
            __nv_bfloat162 ll = __floats2bfloat162_rn(w0 - __low2float(hh),
                                                      w1 - __high2float(hh));
            const size_t rb = (size_t)(b * L_ + k * ST + t) * K2X;
            const int col = h * HD + pstart + p0;
            *(__nv_bfloat162*)&g_y2[rb + col]          = hh;
            *(__nv_bfloat162*)&g_y2[rb + DI + col]     = ll;
            *(__nv_bfloat162*)&g_y2[rb + 2 * DI + col] = hh;
        }
        __syncthreads();
    }
#undef PREFETCH
}

// ---------------- launch ----------------
extern "C" void kernel_launch(void* const* d_in, const int* in_sizes, int n_in,
                              void* d_out, int out_size)
{
    (void)in_sizes; (void)n_in; (void)out_size;
    const float* u        = (const float*)d_in[0];
    const float* W_in     = (const float*)d_in[1];
    const float* W_out    = (const float*)d_in[2];
    const float* dt_bias  = (const float*)d_in[3];
    const float* B_bias   = (const float*)d_in[4];
    const float* C_bias   = (const float*)d_in[5];
    const float* B_norm_w = (const float*)d_in[6];
    const float* C_norm_w = (const float*)d_in[7];
    const float* D_param  = (const float*)d_in[8];
    float* out = (float*)d_out;

    void *p_proj, *p_u2, *p_wi2, *p_y2, *p_wo2;
    cudaGetSymbolAddress(&p_proj, g_proj);
    cudaGetSymbolAddress(&p_u2,  g_u2);
    cudaGetSymbolAddress(&p_wi2, g_Wi2);
    cudaGetSymbolAddress(&p_y2,  g_y2);
    cudaGetSymbolAddress(&p_wo2, g_Wo2);

    cudaFuncSetAttribute(gemm_bf16, cudaFuncAttributeMaxDynamicSharedMemorySize, GS_TOTAL);
    cudaFuncSetAttribute(scan_kernel, cudaFuncAttributeMaxDynamicSharedMemorySize, SCAN_SMEM_BYTES);

    // 0) splits needed for GEMM1
    split_A<<<(BT * DM / 4 + 255) / 256, 256>>>(u,    (__nv_bfloat16*)p_u2,  DM / 4, BT * DM / 4);   // launch 0
    split_B<<<(DP * DM / 4 + 255) / 256, 256>>>(W_in, (__nv_bfloat16*)p_wi2, DM / 4, DP * DM / 4);   // launch 1

    // 1) proj = u @ W_in^T
    gemm_bf16<<<dim3(DP / 128, BT / 128), 256, GS_TOTAL>>>(
        (const __nv_bfloat16*)p_u2, (const __nv_bfloat16*)p_wi2,
        (float*)p_proj, BT, DP, K1X);                                                                // launch 2

    // 2) rmsnorm + head scalars
    prep_kernel<<<BT, 128>>>(dt_bias, B_norm_w, C_norm_w);                                           // launch 3

    // 3) theta (single kernel)
    theta_kernel<<<dim3(NH, B_), 1024>>>();                                                          // launch 4

    // 4) scan + fused gated epilogue  (launch index 5 -> captured by ncu -s 5 -c 1)
    scan_kernel<<<dim3(2, NH, B_), 256, SCAN_SMEM_BYTES>>>(B_bias, C_bias, D_param);                 // launch 5

    // 5) split for GEMM2 (independent of scan; placed after to keep scan at index 5)
    split_B<<<(DM * DI / 4 + 255) / 256, 256>>>(W_out, (__nv_bfloat16*)p_wo2, DI / 4, DM * DI / 4);  // launch 6

    // 6) out = yact @ W_out^T
    gemm_bf16<<<dim3(DM / 128, BT / 128), 256, GS_TOTAL>>>(
        (const __nv_bfloat16*)p_y2, (const __nv_bfloat16*)p_wo2,
        out, BT, DM, K2X);                                                                           // launch 7
}